// round 1
// baseline (speedup 1.0000x reference)
#include <cuda_runtime.h>
#include <cstdint>

#define BSZ 2
#define SEQ 2048
#define DIM 768
#define NH 12
#define HD 64
#define M_TOT (BSZ * SEQ)   // 4096
#define NQKV (3 * DIM)      // 2304

// Scratch (allocation-free rule: __device__ globals)
__device__ float g_q[(size_t)BSZ * NH * SEQ * HD];
__device__ float g_k[(size_t)BSZ * NH * SEQ * HD];
__device__ float g_v[(size_t)BSZ * NH * SEQ * HD];
__device__ float g_attn[(size_t)BSZ * SEQ * DIM];

__device__ __forceinline__ float neg_inf() { return __int_as_float(0xff800000u); }

// ---------------------------------------------------------------------------
// GEMM 1: [4096,768] @ [768,2304] + bias -> scatter to Q/K/V [b,h,s,d]
// 128x128 tile, BK=16, 256 threads, 8x8 per thread.
// ---------------------------------------------------------------------------
__global__ void __launch_bounds__(256, 2) gemm_qkv_kernel(
    const float* __restrict__ A, const float* __restrict__ W,
    const float* __restrict__ bias)
{
    __shared__ float As[16][128];   // transposed A tile: As[k][m]
    __shared__ float Bs[16][128];

    const int tid = threadIdx.x;
    const int m0 = blockIdx.y * 128;
    const int n0 = blockIdx.x * 128;
    const int arow = tid >> 2;             // 0..63
    const int acol = (tid & 3) << 2;       // 0,4,8,12
    const int brow = tid >> 5;             // 0..7
    const int bcol = (tid & 31) << 2;      // 0..124
    const int ty = tid >> 4, tx = tid & 15;

    float acc[8][8];
#pragma unroll
    for (int i = 0; i < 8; ++i)
#pragma unroll
        for (int j = 0; j < 8; ++j) acc[i][j] = 0.f;

    for (int k0 = 0; k0 < DIM; k0 += 16) {
#pragma unroll
        for (int hh = 0; hh < 2; ++hh) {
            const float4 a = *(const float4*)&A[(size_t)(m0 + arow + hh * 64) * DIM + k0 + acol];
            As[acol + 0][arow + hh * 64] = a.x;
            As[acol + 1][arow + hh * 64] = a.y;
            As[acol + 2][arow + hh * 64] = a.z;
            As[acol + 3][arow + hh * 64] = a.w;
            *(float4*)&Bs[brow + hh * 8][bcol] =
                *(const float4*)&W[(size_t)(k0 + brow + hh * 8) * NQKV + n0 + bcol];
        }
        __syncthreads();
#pragma unroll
        for (int kk = 0; kk < 16; ++kk) {
            float ra[8], rb[8];
            *(float4*)&ra[0] = *(const float4*)&As[kk][ty * 8];
            *(float4*)&ra[4] = *(const float4*)&As[kk][ty * 8 + 4];
            *(float4*)&rb[0] = *(const float4*)&Bs[kk][tx * 8];
            *(float4*)&rb[4] = *(const float4*)&Bs[kk][tx * 8 + 4];
#pragma unroll
            for (int i = 0; i < 8; ++i)
#pragma unroll
                for (int j = 0; j < 8; ++j) acc[i][j] += ra[i] * rb[j];
        }
        __syncthreads();
    }

#pragma unroll
    for (int i = 0; i < 8; ++i) {
        const int m = m0 + ty * 8 + i;
        const int bb = m >> 11;           // / SEQ
        const int ss = m & (SEQ - 1);
#pragma unroll
        for (int j = 0; j < 8; ++j) {
            const int n = n0 + tx * 8 + j;
            const float c = acc[i][j] + bias[n];
            const int which = n / DIM;
            const int rem = n - which * DIM;
            const int h = rem >> 6, d = rem & 63;
            float* dst = (which == 0) ? g_q : (which == 1) ? g_k : g_v;
            dst[(((size_t)bb * NH + h) * SEQ + ss) * HD + d] = c;
        }
    }
}

// ---------------------------------------------------------------------------
// GEMM 2: g_attn [4096,768] @ W_proj [768,768] + bias -> d_out
// ---------------------------------------------------------------------------
__global__ void __launch_bounds__(256, 2) gemm_proj_kernel(
    const float* __restrict__ W, const float* __restrict__ bias,
    float* __restrict__ out)
{
    __shared__ float As[16][128];
    __shared__ float Bs[16][128];

    const int tid = threadIdx.x;
    const int m0 = blockIdx.y * 128;
    const int n0 = blockIdx.x * 128;
    const int arow = tid >> 2;
    const int acol = (tid & 3) << 2;
    const int brow = tid >> 5;
    const int bcol = (tid & 31) << 2;
    const int ty = tid >> 4, tx = tid & 15;

    float acc[8][8];
#pragma unroll
    for (int i = 0; i < 8; ++i)
#pragma unroll
        for (int j = 0; j < 8; ++j) acc[i][j] = 0.f;

    for (int k0 = 0; k0 < DIM; k0 += 16) {
#pragma unroll
        for (int hh = 0; hh < 2; ++hh) {
            const float4 a = *(const float4*)&g_attn[(size_t)(m0 + arow + hh * 64) * DIM + k0 + acol];
            As[acol + 0][arow + hh * 64] = a.x;
            As[acol + 1][arow + hh * 64] = a.y;
            As[acol + 2][arow + hh * 64] = a.z;
            As[acol + 3][arow + hh * 64] = a.w;
            *(float4*)&Bs[brow + hh * 8][bcol] =
                *(const float4*)&W[(size_t)(k0 + brow + hh * 8) * DIM + n0 + bcol];
        }
        __syncthreads();
#pragma unroll
        for (int kk = 0; kk < 16; ++kk) {
            float ra[8], rb[8];
            *(float4*)&ra[0] = *(const float4*)&As[kk][ty * 8];
            *(float4*)&ra[4] = *(const float4*)&As[kk][ty * 8 + 4];
            *(float4*)&rb[0] = *(const float4*)&Bs[kk][tx * 8];
            *(float4*)&rb[4] = *(const float4*)&Bs[kk][tx * 8 + 4];
#pragma unroll
            for (int i = 0; i < 8; ++i)
#pragma unroll
                for (int j = 0; j < 8; ++j) acc[i][j] += ra[i] * rb[j];
        }
        __syncthreads();
    }

#pragma unroll
    for (int i = 0; i < 8; ++i) {
        const int m = m0 + ty * 8 + i;
#pragma unroll
        for (int j = 0; j < 8; ++j) {
            const int n = n0 + tx * 8 + j;
            out[(size_t)m * DIM + n] = acc[i][j] + bias[n];
        }
    }
}

// ---------------------------------------------------------------------------
// Flash attention (fp32, causal). One block = 64 queries of one (b,h).
// 256 threads = 64 rows x 4 lanes. Online softmax; K-tile smem reused for P.
// Lane c4 owns j = c4 + 4*jj (scores) and d = 16q + 4*c4 + i (output).
// ---------------------------------------------------------------------------
__global__ void __launch_bounds__(256, 2) attn_kernel()
{
    __shared__ float KP[64][68];   // K tile (padded), later reused as P tile
    __shared__ float Vt[64][64];   // V tile

    const int qt = gridDim.x - 1 - blockIdx.x;   // heavy tiles first
    const int bh = blockIdx.y;
    const float* Qb = g_q + (size_t)bh * SEQ * HD;
    const float* Kb = g_k + (size_t)bh * SEQ * HD;
    const float* Vb = g_v + (size_t)bh * SEQ * HD;

    const int tid = threadIdx.x;
    const int r = tid >> 2;        // row within tile
    const int c4 = tid & 3;        // lane within row-group
    const int qrow = qt * 64 + r;

    // Q row -> registers
    float qreg[64];
#pragma unroll
    for (int k4 = 0; k4 < 16; ++k4)
        *(float4*)&qreg[k4 * 4] = *(const float4*)&Qb[(size_t)qrow * HD + k4 * 4];

    float o[16];
#pragma unroll
    for (int i = 0; i < 16; ++i) o[i] = 0.f;
    float m_i = neg_inf(), l_i = 0.f;

    const int jrow = tid >> 4;            // loader: 0..15
    const int kc = (tid & 15) << 2;       // loader col: 0..60

    for (int kt = 0; kt <= qt; ++kt) {
        // Load K and V tiles (coalesced float4)
#pragma unroll
        for (int l = 0; l < 4; ++l) {
            const int j = jrow + l * 16;
            const size_t g = ((size_t)kt * 64 + j) * HD + kc;
            *(float4*)&KP[j][kc] = *(const float4*)&Kb[g];
            *(float4*)&Vt[j][kc] = *(const float4*)&Vb[g];
        }
        __syncthreads();

        // S = Q K^T (scaled) + causal mask; lane owns j = c4 + 4*jj
        float sv[16];
#pragma unroll
        for (int jj = 0; jj < 16; ++jj) {
            const int j = c4 + (jj << 2);
            float a = 0.f;
#pragma unroll
            for (int k4 = 0; k4 < 16; ++k4) {
                const float4 kk4 = *(const float4*)&KP[j][k4 * 4];
                a += qreg[k4 * 4 + 0] * kk4.x;
                a += qreg[k4 * 4 + 1] * kk4.y;
                a += qreg[k4 * 4 + 2] * kk4.z;
                a += qreg[k4 * 4 + 3] * kk4.w;
            }
            sv[jj] = (kt * 64 + j <= qrow) ? a * 0.125f : neg_inf();
        }

        // Row max across 16 local + 4-lane shfl group
        float mt = sv[0];
#pragma unroll
        for (int jj = 1; jj < 16; ++jj) mt = fmaxf(mt, sv[jj]);
        mt = fmaxf(mt, __shfl_xor_sync(0xffffffffu, mt, 1));
        mt = fmaxf(mt, __shfl_xor_sync(0xffffffffu, mt, 2));
        const float m_new = fmaxf(m_i, mt);
        const float corr = __expf(m_i - m_new);

        float psum = 0.f;
#pragma unroll
        for (int jj = 0; jj < 16; ++jj) {
            const float p = __expf(sv[jj] - m_new);
            sv[jj] = p;
            psum += p;
        }
        psum += __shfl_xor_sync(0xffffffffu, psum, 1);
        psum += __shfl_xor_sync(0xffffffffu, psum, 2);
        l_i = l_i * corr + psum;
        m_i = m_new;
#pragma unroll
        for (int i = 0; i < 16; ++i) o[i] *= corr;

        __syncthreads();   // all S reads of KP done -> safe to overwrite as P

        // Write P into KP
#pragma unroll
        for (int jj = 0; jj < 16; ++jj)
            KP[r][c4 + (jj << 2)] = sv[jj];
        __syncwarp();      // P row is produced/consumed within one warp

        // O += P @ V ; lane owns d = 16q + 4*c4 + i
#pragma unroll
        for (int j4 = 0; j4 < 16; ++j4) {
            const float4 p4 = *(const float4*)&KP[r][j4 * 4];
#pragma unroll
            for (int e = 0; e < 4; ++e) {
                const float p = (e == 0) ? p4.x : (e == 1) ? p4.y : (e == 2) ? p4.z : p4.w;
                const int j = j4 * 4 + e;
#pragma unroll
                for (int q = 0; q < 4; ++q) {
                    const float4 v4 = *(const float4*)&Vt[j][q * 16 + c4 * 4];
                    o[q * 4 + 0] += p * v4.x;
                    o[q * 4 + 1] += p * v4.y;
                    o[q * 4 + 2] += p * v4.z;
                    o[q * 4 + 3] += p * v4.w;
                }
            }
        }
        __syncthreads();   // before next tile overwrites KP/Vt
    }

    const float inv = 1.f / l_i;
    const int bb = bh / NH, h = bh % NH;
    float* Ob = g_attn + ((size_t)bb * SEQ + qrow) * DIM + h * HD;
#pragma unroll
    for (int q = 0; q < 4; ++q) {
        float4 w;
        w.x = o[q * 4 + 0] * inv;
        w.y = o[q * 4 + 1] * inv;
        w.z = o[q * 4 + 2] * inv;
        w.w = o[q * 4 + 3] * inv;
        *(float4*)&Ob[q * 16 + c4 * 4] = w;
    }
}

// ---------------------------------------------------------------------------
extern "C" void kernel_launch(void* const* d_in, const int* in_sizes, int n_in,
                              void* d_out, int out_size)
{
    const float* x     = (const float*)d_in[0];
    const float* Wqkv  = (const float*)d_in[1];
    const float* bqkv  = (const float*)d_in[2];
    const float* Wproj = (const float*)d_in[3];
    const float* bproj = (const float*)d_in[4];
    float* out = (float*)d_out;

    gemm_qkv_kernel<<<dim3(NQKV / 128, M_TOT / 128), 256>>>(x, Wqkv, bqkv);
    attn_kernel<<<dim3(SEQ / 64, BSZ * NH), 256>>>();
    gemm_proj_kernel<<<dim3(DIM / 128, M_TOT / 128), 256>>>(Wproj, bproj, out);
}

// round 2
// speedup vs baseline: 1.0476x; 1.0476x over previous
#include <cuda_runtime.h>
#include <cstdint>

#define BSZ 2
#define SEQ 2048
#define DIM 768
#define NH 12
#define HD 64
#define M_TOT (BSZ * SEQ)   // 4096
#define NQKV (3 * DIM)      // 2304

// Scratch (allocation-free rule: __device__ globals)
__device__ float g_q[(size_t)BSZ * NH * SEQ * HD];
__device__ float g_k[(size_t)BSZ * NH * SEQ * HD];
__device__ float g_v[(size_t)BSZ * NH * SEQ * HD];
__device__ float g_attn[(size_t)BSZ * SEQ * DIM];

__device__ __forceinline__ float neg_inf() { return __int_as_float(0xff800000u); }

// ---------------------------------------------------------------------------
// GEMM 1: [4096,768] @ [768,2304] + bias -> scatter to Q/K/V [b,h,s,d]
// ---------------------------------------------------------------------------
__global__ void __launch_bounds__(256, 2) gemm_qkv_kernel(
    const float* __restrict__ A, const float* __restrict__ W,
    const float* __restrict__ bias)
{
    __shared__ float As[16][128];   // transposed A tile: As[k][m]
    __shared__ float Bs[16][128];

    const int tid = threadIdx.x;
    const int m0 = blockIdx.y * 128;
    const int n0 = blockIdx.x * 128;
    const int arow = tid >> 2;
    const int acol = (tid & 3) << 2;
    const int brow = tid >> 5;
    const int bcol = (tid & 31) << 2;
    const int ty = tid >> 4, tx = tid & 15;

    float acc[8][8];
#pragma unroll
    for (int i = 0; i < 8; ++i)
#pragma unroll
        for (int j = 0; j < 8; ++j) acc[i][j] = 0.f;

    for (int k0 = 0; k0 < DIM; k0 += 16) {
#pragma unroll
        for (int hh = 0; hh < 2; ++hh) {
            const float4 a = *(const float4*)&A[(size_t)(m0 + arow + hh * 64) * DIM + k0 + acol];
            As[acol + 0][arow + hh * 64] = a.x;
            As[acol + 1][arow + hh * 64] = a.y;
            As[acol + 2][arow + hh * 64] = a.z;
            As[acol + 3][arow + hh * 64] = a.w;
            *(float4*)&Bs[brow + hh * 8][bcol] =
                *(const float4*)&W[(size_t)(k0 + brow + hh * 8) * NQKV + n0 + bcol];
        }
        __syncthreads();
#pragma unroll
        for (int kk = 0; kk < 16; ++kk) {
            float ra[8], rb[8];
            *(float4*)&ra[0] = *(const float4*)&As[kk][ty * 8];
            *(float4*)&ra[4] = *(const float4*)&As[kk][ty * 8 + 4];
            *(float4*)&rb[0] = *(const float4*)&Bs[kk][tx * 8];
            *(float4*)&rb[4] = *(const float4*)&Bs[kk][tx * 8 + 4];
#pragma unroll
            for (int i = 0; i < 8; ++i)
#pragma unroll
                for (int j = 0; j < 8; ++j) acc[i][j] += ra[i] * rb[j];
        }
        __syncthreads();
    }

#pragma unroll
    for (int i = 0; i < 8; ++i) {
        const int m = m0 + ty * 8 + i;
        const int bb = m >> 11;
        const int ss = m & (SEQ - 1);
#pragma unroll
        for (int j = 0; j < 8; ++j) {
            const int n = n0 + tx * 8 + j;
            const float c = acc[i][j] + bias[n];
            const int which = n / DIM;
            const int rem = n - which * DIM;
            const int h = rem >> 6, d = rem & 63;
            float* dst = (which == 0) ? g_q : (which == 1) ? g_k : g_v;
            dst[(((size_t)bb * NH + h) * SEQ + ss) * HD + d] = c;
        }
    }
}

// ---------------------------------------------------------------------------
// GEMM 2: g_attn [4096,768] @ W_proj [768,768] + bias -> d_out
// ---------------------------------------------------------------------------
__global__ void __launch_bounds__(256, 2) gemm_proj_kernel(
    const float* __restrict__ W, const float* __restrict__ bias,
    float* __restrict__ out)
{
    __shared__ float As[16][128];
    __shared__ float Bs[16][128];

    const int tid = threadIdx.x;
    const int m0 = blockIdx.y * 128;
    const int n0 = blockIdx.x * 128;
    const int arow = tid >> 2;
    const int acol = (tid & 3) << 2;
    const int brow = tid >> 5;
    const int bcol = (tid & 31) << 2;
    const int ty = tid >> 4, tx = tid & 15;

    float acc[8][8];
#pragma unroll
    for (int i = 0; i < 8; ++i)
#pragma unroll
        for (int j = 0; j < 8; ++j) acc[i][j] = 0.f;

    for (int k0 = 0; k0 < DIM; k0 += 16) {
#pragma unroll
        for (int hh = 0; hh < 2; ++hh) {
            const float4 a = *(const float4*)&g_attn[(size_t)(m0 + arow + hh * 64) * DIM + k0 + acol];
            As[acol + 0][arow + hh * 64] = a.x;
            As[acol + 1][arow + hh * 64] = a.y;
            As[acol + 2][arow + hh * 64] = a.z;
            As[acol + 3][arow + hh * 64] = a.w;
            *(float4*)&Bs[brow + hh * 8][bcol] =
                *(const float4*)&W[(size_t)(k0 + brow + hh * 8) * DIM + n0 + bcol];
        }
        __syncthreads();
#pragma unroll
        for (int kk = 0; kk < 16; ++kk) {
            float ra[8], rb[8];
            *(float4*)&ra[0] = *(const float4*)&As[kk][ty * 8];
            *(float4*)&ra[4] = *(const float4*)&As[kk][ty * 8 + 4];
            *(float4*)&rb[0] = *(const float4*)&Bs[kk][tx * 8];
            *(float4*)&rb[4] = *(const float4*)&Bs[kk][tx * 8 + 4];
#pragma unroll
            for (int i = 0; i < 8; ++i)
#pragma unroll
                for (int j = 0; j < 8; ++j) acc[i][j] += ra[i] * rb[j];
        }
        __syncthreads();
    }

#pragma unroll
    for (int i = 0; i < 8; ++i) {
        const int m = m0 + ty * 8 + i;
#pragma unroll
        for (int j = 0; j < 8; ++j) {
            const int n = n0 + tx * 8 + j;
            out[(size_t)m * DIM + n] = acc[i][j] + bias[n];
        }
    }
}

// ---------------------------------------------------------------------------
// Flash attention v2 (fp32, causal).
// Block = 128 queries x one (b,h). 256 threads as 16(ty) x 16(tx).
// Thread micro-tile: 8 rows (ty*8..+7) x 4 cols (tx*4..+3).
// Q tile resident in smem for whole block; K stored k-major; P via smem.
// ---------------------------------------------------------------------------
#define BQ 128
#define BK 64
#define QS_LD 68
#define KS_LD 68
#define VS_LD 64
#define PS_LD 68
#define ATTN_SMEM_FLOATS (BQ * QS_LD + BK * KS_LD + BK * VS_LD + BQ * PS_LD)
#define ATTN_SMEM_BYTES (ATTN_SMEM_FLOATS * 4)

__global__ void __launch_bounds__(256, 2) attn2_kernel()
{
    extern __shared__ float sm[];
    float* Qs = sm;                        // [BQ][QS_LD]
    float* Ks = Qs + BQ * QS_LD;           // [BK][KS_LD]  (k-major: Ks[k][j])
    float* Vs = Ks + BK * KS_LD;           // [BK][VS_LD]  (Vs[j][d])
    float* Ps = Vs + BK * VS_LD;           // [BQ][PS_LD]

    const int bh = blockIdx.x;             // 0..23
    const int qi = (gridDim.y - 1) - blockIdx.y;  // heavy tiles scheduled first
    const int q0 = qi * BQ;
    const int nt = 2 * qi + 2;             // # key tiles for this block

    const float* Qb = g_q + (size_t)bh * SEQ * HD;
    const float* Kb = g_k + (size_t)bh * SEQ * HD;
    const float* Vb = g_v + (size_t)bh * SEQ * HD;

    const int tid = threadIdx.x;
    const int ty = tid >> 4;               // 0..15 (row group)
    const int tx = tid & 15;               // 0..15 (col group)
    const int r0 = ty * 8;

    // ---- load Q tile once (natural layout, rows padded) ----
#pragma unroll
    for (int t = 0; t < 8; ++t) {
        const int f = tid + t * 256;       // 2048 float4 total
        const int m = f >> 4;
        const int c4 = (f & 15) << 2;
        *(float4*)&Qs[m * QS_LD + c4] = *(const float4*)&Qb[((size_t)q0 + m) * HD + c4];
    }

    float o[8][4];
#pragma unroll
    for (int i = 0; i < 8; ++i)
#pragma unroll
        for (int d = 0; d < 4; ++d) o[i][d] = 0.f;
    float mrow[8], lrow[8];
#pragma unroll
    for (int i = 0; i < 8; ++i) { mrow[i] = neg_inf(); lrow[i] = 0.f; }

    for (int kt = 0; kt < nt; ++kt) {
        __syncthreads();   // previous PV reads of Ks/Vs/Ps complete
        // ---- load K (transposed to k-major) and V (natural) ----
#pragma unroll
        for (int t = 0; t < 4; ++t) {
            const int f = tid + t * 256;   // 1024 float4 total
            const int j = f >> 4;
            const int c4 = (f & 15) << 2;
            const size_t g = ((size_t)kt * BK + j) * HD + c4;
            const float4 kq = *(const float4*)&Kb[g];
            const float4 vq = *(const float4*)&Vb[g];
            *(float4*)&Vs[j * VS_LD + c4] = vq;
            Ks[(c4 + 0) * KS_LD + j] = kq.x;
            Ks[(c4 + 1) * KS_LD + j] = kq.y;
            Ks[(c4 + 2) * KS_LD + j] = kq.z;
            Ks[(c4 + 3) * KS_LD + j] = kq.w;
        }
        __syncthreads();

        const bool need_mask = (kt >= nt - 2);

        // ---- S = Q K^T, softmax, P -> smem; two row-halves to cap registers ----
#pragma unroll
        for (int half = 0; half < 2; ++half) {
            const int rb = r0 + half * 4;
            float sv[4][4];
#pragma unroll
            for (int i = 0; i < 4; ++i)
#pragma unroll
                for (int jj = 0; jj < 4; ++jj) sv[i][jj] = 0.f;

#pragma unroll
            for (int k4 = 0; k4 < 16; ++k4) {
                float4 kv[4];
#pragma unroll
                for (int e = 0; e < 4; ++e)
                    kv[e] = *(const float4*)&Ks[(k4 * 4 + e) * KS_LD + tx * 4];
#pragma unroll
                for (int i = 0; i < 4; ++i) {
                    const float4 q = *(const float4*)&Qs[(rb + i) * QS_LD + k4 * 4];
                    sv[i][0] += q.x * kv[0].x; sv[i][1] += q.x * kv[0].y;
                    sv[i][2] += q.x * kv[0].z; sv[i][3] += q.x * kv[0].w;
                    sv[i][0] += q.y * kv[1].x; sv[i][1] += q.y * kv[1].y;
                    sv[i][2] += q.y * kv[1].z; sv[i][3] += q.y * kv[1].w;
                    sv[i][0] += q.z * kv[2].x; sv[i][1] += q.z * kv[2].y;
                    sv[i][2] += q.z * kv[2].z; sv[i][3] += q.z * kv[2].w;
                    sv[i][0] += q.w * kv[3].x; sv[i][1] += q.w * kv[3].y;
                    sv[i][2] += q.w * kv[3].z; sv[i][3] += q.w * kv[3].w;
                }
            }

#pragma unroll
            for (int i = 0; i < 4; ++i) {
                const int gi = half * 4 + i;
                const int rg = q0 + rb + i;
                float s0 = sv[i][0] * 0.125f, s1 = sv[i][1] * 0.125f;
                float s2 = sv[i][2] * 0.125f, s3 = sv[i][3] * 0.125f;
                if (need_mask) {
                    const int kg = kt * BK + tx * 4;
                    if (kg + 0 > rg) s0 = neg_inf();
                    if (kg + 1 > rg) s1 = neg_inf();
                    if (kg + 2 > rg) s2 = neg_inf();
                    if (kg + 3 > rg) s3 = neg_inf();
                }
                float mt = fmaxf(fmaxf(s0, s1), fmaxf(s2, s3));
                mt = fmaxf(mt, __shfl_xor_sync(0xffffffffu, mt, 1));
                mt = fmaxf(mt, __shfl_xor_sync(0xffffffffu, mt, 2));
                mt = fmaxf(mt, __shfl_xor_sync(0xffffffffu, mt, 4));
                mt = fmaxf(mt, __shfl_xor_sync(0xffffffffu, mt, 8));
                const float mn = fmaxf(mrow[gi], mt);
                const float corr = __expf(mrow[gi] - mn);
                const float p0 = __expf(s0 - mn);
                const float p1 = __expf(s1 - mn);
                const float p2 = __expf(s2 - mn);
                const float p3 = __expf(s3 - mn);
                float rs = p0 + p1 + p2 + p3;
                rs += __shfl_xor_sync(0xffffffffu, rs, 1);
                rs += __shfl_xor_sync(0xffffffffu, rs, 2);
                rs += __shfl_xor_sync(0xffffffffu, rs, 4);
                rs += __shfl_xor_sync(0xffffffffu, rs, 8);
                lrow[gi] = lrow[gi] * corr + rs;
                mrow[gi] = mn;
                o[gi][0] *= corr; o[gi][1] *= corr;
                o[gi][2] *= corr; o[gi][3] *= corr;
                *(float4*)&Ps[(rb + i) * PS_LD + tx * 4] = make_float4(p0, p1, p2, p3);
            }
        }
        __syncthreads();   // P fully written

        // ---- O += P @ V ----
#pragma unroll
        for (int js = 0; js < 16; ++js) {
            float4 vv[4];
#pragma unroll
            for (int e = 0; e < 4; ++e)
                vv[e] = *(const float4*)&Vs[(js * 4 + e) * VS_LD + tx * 4];
#pragma unroll
            for (int i = 0; i < 8; ++i) {
                const float4 pp = *(const float4*)&Ps[(r0 + i) * PS_LD + js * 4];
                o[i][0] += pp.x * vv[0].x; o[i][1] += pp.x * vv[0].y;
                o[i][2] += pp.x * vv[0].z; o[i][3] += pp.x * vv[0].w;
                o[i][0] += pp.y * vv[1].x; o[i][1] += pp.y * vv[1].y;
                o[i][2] += pp.y * vv[1].z; o[i][3] += pp.y * vv[1].w;
                o[i][0] += pp.z * vv[2].x; o[i][1] += pp.z * vv[2].y;
                o[i][2] += pp.z * vv[2].z; o[i][3] += pp.z * vv[2].w;
                o[i][0] += pp.w * vv[3].x; o[i][1] += pp.w * vv[3].y;
                o[i][2] += pp.w * vv[3].z; o[i][3] += pp.w * vv[3].w;
            }
        }
    }

    // ---- write normalized output ----
    const int bb = bh / NH;
    const int h = bh - bb * NH;
#pragma unroll
    for (int i = 0; i < 8; ++i) {
        const float inv = 1.f / lrow[i];
        float4 w;
        w.x = o[i][0] * inv; w.y = o[i][1] * inv;
        w.z = o[i][2] * inv; w.w = o[i][3] * inv;
        *(float4*)&g_attn[((size_t)(bb * SEQ) + q0 + r0 + i) * DIM + h * HD + tx * 4] = w;
    }
}

// ---------------------------------------------------------------------------
extern "C" void kernel_launch(void* const* d_in, const int* in_sizes, int n_in,
                              void* d_out, int out_size)
{
    const float* x     = (const float*)d_in[0];
    const float* Wqkv  = (const float*)d_in[1];
    const float* bqkv  = (const float*)d_in[2];
    const float* Wproj = (const float*)d_in[3];
    const float* bproj = (const float*)d_in[4];
    float* out = (float*)d_out;

    cudaFuncSetAttribute(attn2_kernel,
                         cudaFuncAttributeMaxDynamicSharedMemorySize,
                         ATTN_SMEM_BYTES);

    gemm_qkv_kernel<<<dim3(NQKV / 128, M_TOT / 128), 256>>>(x, Wqkv, bqkv);
    attn2_kernel<<<dim3(BSZ * NH, SEQ / BQ), 256, ATTN_SMEM_BYTES>>>();
    gemm_proj_kernel<<<dim3(DIM / 128, M_TOT / 128), 256>>>(Wproj, bproj, out);
}

// round 3
// speedup vs baseline: 1.8085x; 1.7263x over previous
#include <cuda_runtime.h>
#include <cstdint>

#define BSZ 2
#define SEQ 2048
#define DIM 768
#define NH 12
#define HD 64
#define M_TOT (BSZ * SEQ)   // 4096
#define NQKV (3 * DIM)      // 2304

// Scratch (allocation-free rule: __device__ globals)
// Q and K stored k-major: [bh][d][s]  (transposed by the QKV GEMM epilogue)
__device__ float g_qT[(size_t)BSZ * NH * HD * SEQ];
__device__ float g_kT[(size_t)BSZ * NH * HD * SEQ];
__device__ float g_v [(size_t)BSZ * NH * SEQ * HD];
__device__ float g_attn[(size_t)BSZ * SEQ * DIM];

__device__ __forceinline__ float neg_inf() { return __int_as_float(0xff800000u); }

// ---------------------------------------------------------------------------
// GEMM 1: [4096,768] @ [768,2304] + bias.
// Q,K scattered k-major ([bh][d][s], f4 along s); V token-major ([bh][s][d]).
// ---------------------------------------------------------------------------
__global__ void __launch_bounds__(256, 2) gemm_qkv_kernel(
    const float* __restrict__ A, const float* __restrict__ W,
    const float* __restrict__ bias)
{
    __shared__ float As[16][128];   // transposed A tile: As[k][m]
    __shared__ float Bs[16][128];

    const int tid = threadIdx.x;
    const int m0 = blockIdx.y * 128;
    const int n0 = blockIdx.x * 128;
    const int arow = tid >> 2;
    const int acol = (tid & 3) << 2;
    const int brow = tid >> 5;
    const int bcol = (tid & 31) << 2;
    const int ty = tid >> 4, tx = tid & 15;

    float acc[8][8];
#pragma unroll
    for (int i = 0; i < 8; ++i)
#pragma unroll
        for (int j = 0; j < 8; ++j) acc[i][j] = 0.f;

    for (int k0 = 0; k0 < DIM; k0 += 16) {
#pragma unroll
        for (int hh = 0; hh < 2; ++hh) {
            const float4 a = *(const float4*)&A[(size_t)(m0 + arow + hh * 64) * DIM + k0 + acol];
            As[acol + 0][arow + hh * 64] = a.x;
            As[acol + 1][arow + hh * 64] = a.y;
            As[acol + 2][arow + hh * 64] = a.z;
            As[acol + 3][arow + hh * 64] = a.w;
            *(float4*)&Bs[brow + hh * 8][bcol] =
                *(const float4*)&W[(size_t)(k0 + brow + hh * 8) * NQKV + n0 + bcol];
        }
        __syncthreads();
#pragma unroll
        for (int kk = 0; kk < 16; ++kk) {
            float ra[8], rb[8];
            *(float4*)&ra[0] = *(const float4*)&As[kk][ty * 8];
            *(float4*)&ra[4] = *(const float4*)&As[kk][ty * 8 + 4];
            *(float4*)&rb[0] = *(const float4*)&Bs[kk][tx * 8];
            *(float4*)&rb[4] = *(const float4*)&Bs[kk][tx * 8 + 4];
#pragma unroll
            for (int i = 0; i < 8; ++i)
#pragma unroll
                for (int j = 0; j < 8; ++j) acc[i][j] += ra[i] * rb[j];
        }
        __syncthreads();
    }

    const int bb = m0 >> 11;                     // batch (tiles never straddle)
    const int sbase = (m0 & (SEQ - 1)) + ty * 8; // token base for this thread
    const int which = n0 / DIM;                  // whole block in one region

    if (which == 2) {
        // V: token-major, f4 along d
#pragma unroll
        for (int i = 0; i < 8; ++i) {
            const int ss = sbase + i;
#pragma unroll
            for (int j4 = 0; j4 < 2; ++j4) {
                const int n = n0 + tx * 8 + j4 * 4;
                const int rem = n - 2 * DIM;
                const int h = rem >> 6, d = rem & 63;
                float4 w;
                w.x = acc[i][j4 * 4 + 0] + bias[n + 0];
                w.y = acc[i][j4 * 4 + 1] + bias[n + 1];
                w.z = acc[i][j4 * 4 + 2] + bias[n + 2];
                w.w = acc[i][j4 * 4 + 3] + bias[n + 3];
                *(float4*)&g_v[(((size_t)bb * NH + h) * SEQ + ss) * HD + d] = w;
            }
        }
    } else {
        // Q/K: k-major [bh][d][s], f4 along tokens
        float* dst = (which == 0) ? g_qT : g_kT;
#pragma unroll
        for (int j = 0; j < 8; ++j) {
            const int n = n0 + tx * 8 + j;
            const int rem = n - which * DIM;
            const int h = rem >> 6, d = rem & 63;
            const float bn = bias[n];
            float* p = &dst[((size_t)(bb * NH + h) * HD + d) * SEQ + sbase];
            float4 w0, w1;
            w0.x = acc[0][j] + bn; w0.y = acc[1][j] + bn;
            w0.z = acc[2][j] + bn; w0.w = acc[3][j] + bn;
            w1.x = acc[4][j] + bn; w1.y = acc[5][j] + bn;
            w1.z = acc[6][j] + bn; w1.w = acc[7][j] + bn;
            *(float4*)&p[0] = w0;
            *(float4*)&p[4] = w1;
        }
    }
}

// ---------------------------------------------------------------------------
// GEMM 2: g_attn [4096,768] @ W_proj [768,768] + bias -> d_out
// ---------------------------------------------------------------------------
__global__ void __launch_bounds__(256, 2) gemm_proj_kernel(
    const float* __restrict__ W, const float* __restrict__ bias,
    float* __restrict__ out)
{
    __shared__ float As[16][128];
    __shared__ float Bs[16][128];

    const int tid = threadIdx.x;
    const int m0 = blockIdx.y * 128;
    const int n0 = blockIdx.x * 128;
    const int arow = tid >> 2;
    const int acol = (tid & 3) << 2;
    const int brow = tid >> 5;
    const int bcol = (tid & 31) << 2;
    const int ty = tid >> 4, tx = tid & 15;

    float acc[8][8];
#pragma unroll
    for (int i = 0; i < 8; ++i)
#pragma unroll
        for (int j = 0; j < 8; ++j) acc[i][j] = 0.f;

    for (int k0 = 0; k0 < DIM; k0 += 16) {
#pragma unroll
        for (int hh = 0; hh < 2; ++hh) {
            const float4 a = *(const float4*)&g_attn[(size_t)(m0 + arow + hh * 64) * DIM + k0 + acol];
            As[acol + 0][arow + hh * 64] = a.x;
            As[acol + 1][arow + hh * 64] = a.y;
            As[acol + 2][arow + hh * 64] = a.z;
            As[acol + 3][arow + hh * 64] = a.w;
            *(float4*)&Bs[brow + hh * 8][bcol] =
                *(const float4*)&W[(size_t)(k0 + brow + hh * 8) * DIM + n0 + bcol];
        }
        __syncthreads();
#pragma unroll
        for (int kk = 0; kk < 16; ++kk) {
            float ra[8], rb[8];
            *(float4*)&ra[0] = *(const float4*)&As[kk][ty * 8];
            *(float4*)&ra[4] = *(const float4*)&As[kk][ty * 8 + 4];
            *(float4*)&rb[0] = *(const float4*)&Bs[kk][tx * 8];
            *(float4*)&rb[4] = *(const float4*)&Bs[kk][tx * 8 + 4];
#pragma unroll
            for (int i = 0; i < 8; ++i)
#pragma unroll
                for (int j = 0; j < 8; ++j) acc[i][j] += ra[i] * rb[j];
        }
        __syncthreads();
    }

#pragma unroll
    for (int i = 0; i < 8; ++i) {
        const int m = m0 + ty * 8 + i;
#pragma unroll
        for (int j = 0; j < 8; ++j) {
            const int n = n0 + tx * 8 + j;
            out[(size_t)m * DIM + n] = acc[i][j] + bias[n];
        }
    }
}

// ---------------------------------------------------------------------------
// Flash attention v3 (fp32, causal).
// Block = 128 queries x one (b,h); 128-key tiles. 256 threads = 16 ty x 16 tx.
// S-phase: 8x8 micro-tile, both operands k-major (0.25 B/FLOP).
// PV-phase: 8 rows x 4 d, broadcast P reads. Softmax rows owned by ty.
// ---------------------------------------------------------------------------
#define BQ 128
#define BKK 128
#define QK_LD 132
#define VS_LD 68
#define PS_LD 132
#define ATTN_SMEM_FLOATS (64 * QK_LD + 64 * QK_LD + BKK * VS_LD + BQ * PS_LD)
#define ATTN_SMEM_BYTES (ATTN_SMEM_FLOATS * 4)

__global__ void __launch_bounds__(256, 1) attn3_kernel()
{
    extern __shared__ float sm[];
    float* Qs = sm;                       // [64][132] k-major: Qs[k][m]
    float* Ks = Qs + 64 * QK_LD;          // [64][132] k-major: Ks[k][j]
    float* Vs = Ks + 64 * QK_LD;          // [128][68]: Vs[j][d]
    float* Ps = Vs + BKK * VS_LD;         // [128][132]: Ps[r][j]

    const int bh = blockIdx.x;
    const int qi = (gridDim.y - 1) - blockIdx.y;   // heavy tiles first
    const int q0 = qi * BQ;

    const float* QTb = g_qT + (size_t)bh * HD * SEQ;
    const float* KTb = g_kT + (size_t)bh * HD * SEQ;
    const float* Vb  = g_v  + (size_t)bh * SEQ * HD;

    const int tid = threadIdx.x;
    const int ty = tid >> 4;              // row group: rows ty*8 .. ty*8+7
    const int tx = tid & 15;
    const int r0 = ty * 8;

    // ---- load Q tile (64 k-rows x 128 tokens), conflict-free f4 ----
#pragma unroll
    for (int t = 0; t < 8; ++t) {
        const int f = tid + t * 256;      // 2048 f4
        const int k = f >> 5;
        const int c4 = (f & 31) << 2;
        *(float4*)&Qs[k * QK_LD + c4] = *(const float4*)&QTb[(size_t)k * SEQ + q0 + c4];
    }

    float o[8][4];
#pragma unroll
    for (int i = 0; i < 8; ++i)
#pragma unroll
        for (int d = 0; d < 4; ++d) o[i][d] = 0.f;
    float mrow[8], lrow[8];
#pragma unroll
    for (int i = 0; i < 8; ++i) { mrow[i] = neg_inf(); lrow[i] = 0.f; }

    for (int kt = 0; kt <= qi; ++kt) {
        __syncthreads();    // previous iteration's reads of Ks/Vs complete

        // ---- load K tile (k-major rows) and V tile ----
#pragma unroll
        for (int t = 0; t < 8; ++t) {
            const int f = tid + t * 256;
            const int k = f >> 5;
            const int c4 = (f & 31) << 2;
            *(float4*)&Ks[k * QK_LD + c4] =
                *(const float4*)&KTb[(size_t)k * SEQ + kt * BKK + c4];
        }
#pragma unroll
        for (int t = 0; t < 8; ++t) {
            const int f = tid + t * 256;
            const int j = f >> 4;
            const int d4 = (f & 15) << 2;
            *(float4*)&Vs[j * VS_LD + d4] =
                *(const float4*)&Vb[((size_t)kt * BKK + j) * HD + d4];
        }
        __syncthreads();

        // ---- S = Q^T-tile . K-tile : 8x8 micro ----
        float sv[8][8];
#pragma unroll
        for (int i = 0; i < 8; ++i)
#pragma unroll
            for (int j = 0; j < 8; ++j) sv[i][j] = 0.f;

#pragma unroll 8
        for (int k = 0; k < HD; ++k) {
            float qv[8], kv[8];
            *(float4*)&qv[0] = *(const float4*)&Qs[k * QK_LD + r0];
            *(float4*)&qv[4] = *(const float4*)&Qs[k * QK_LD + r0 + 4];
            *(float4*)&kv[0] = *(const float4*)&Ks[k * QK_LD + tx * 8];
            *(float4*)&kv[4] = *(const float4*)&Ks[k * QK_LD + tx * 8 + 4];
#pragma unroll
            for (int i = 0; i < 8; ++i)
#pragma unroll
                for (int j = 0; j < 8; ++j) sv[i][j] += qv[i] * kv[j];
        }

        // ---- softmax (rows r0..r0+7; reduce across 16 tx lanes) ----
        const bool diag = (kt == qi);
#pragma unroll
        for (int i = 0; i < 8; ++i) {
            float s[8];
#pragma unroll
            for (int j = 0; j < 8; ++j) s[j] = sv[i][j] * 0.125f;
            if (diag) {
                const int rl = r0 + i;
#pragma unroll
                for (int j = 0; j < 8; ++j)
                    if (tx * 8 + j > rl) s[j] = neg_inf();
            }
            float mt = s[0];
#pragma unroll
            for (int j = 1; j < 8; ++j) mt = fmaxf(mt, s[j]);
            mt = fmaxf(mt, __shfl_xor_sync(0xffffffffu, mt, 1));
            mt = fmaxf(mt, __shfl_xor_sync(0xffffffffu, mt, 2));
            mt = fmaxf(mt, __shfl_xor_sync(0xffffffffu, mt, 4));
            mt = fmaxf(mt, __shfl_xor_sync(0xffffffffu, mt, 8));
            const float mn = fmaxf(mrow[i], mt);
            const float corr = __expf(mrow[i] - mn);
            float rs = 0.f;
#pragma unroll
            for (int j = 0; j < 8; ++j) {
                s[j] = __expf(s[j] - mn);
                rs += s[j];
            }
            rs += __shfl_xor_sync(0xffffffffu, rs, 1);
            rs += __shfl_xor_sync(0xffffffffu, rs, 2);
            rs += __shfl_xor_sync(0xffffffffu, rs, 4);
            rs += __shfl_xor_sync(0xffffffffu, rs, 8);
            lrow[i] = lrow[i] * corr + rs;
            mrow[i] = mn;
            o[i][0] *= corr; o[i][1] *= corr; o[i][2] *= corr; o[i][3] *= corr;
            *(float4*)&Ps[(r0 + i) * PS_LD + tx * 8] =
                make_float4(s[0], s[1], s[2], s[3]);
            *(float4*)&Ps[(r0 + i) * PS_LD + tx * 8 + 4] =
                make_float4(s[4], s[5], s[6], s[7]);
        }
        __syncwarp();   // P rows produced & consumed within the same half-warp

        // ---- O += P @ V : 8 rows x 4 d, broadcast P reads ----
#pragma unroll 2
        for (int j4 = 0; j4 < BKK / 4; ++j4) {
            float4 vv[4];
#pragma unroll
            for (int e = 0; e < 4; ++e)
                vv[e] = *(const float4*)&Vs[(j4 * 4 + e) * VS_LD + tx * 4];
#pragma unroll
            for (int i = 0; i < 8; ++i) {
                const float4 pp = *(const float4*)&Ps[(r0 + i) * PS_LD + j4 * 4];
                o[i][0] += pp.x * vv[0].x; o[i][1] += pp.x * vv[0].y;
                o[i][2] += pp.x * vv[0].z; o[i][3] += pp.x * vv[0].w;
                o[i][0] += pp.y * vv[1].x; o[i][1] += pp.y * vv[1].y;
                o[i][2] += pp.y * vv[1].z; o[i][3] += pp.y * vv[1].w;
                o[i][0] += pp.z * vv[2].x; o[i][1] += pp.z * vv[2].y;
                o[i][2] += pp.z * vv[2].z; o[i][3] += pp.z * vv[2].w;
                o[i][0] += pp.w * vv[3].x; o[i][1] += pp.w * vv[3].y;
                o[i][2] += pp.w * vv[3].z; o[i][3] += pp.w * vv[3].w;
            }
        }
    }

    // ---- write normalized output ----
    const int bb = bh / NH;
    const int h = bh - bb * NH;
#pragma unroll
    for (int i = 0; i < 8; ++i) {
        const float inv = 1.f / lrow[i];
        float4 w;
        w.x = o[i][0] * inv; w.y = o[i][1] * inv;
        w.z = o[i][2] * inv; w.w = o[i][3] * inv;
        *(float4*)&g_attn[((size_t)(bb * SEQ) + q0 + r0 + i) * DIM + h * HD + tx * 4] = w;
    }
}

// ---------------------------------------------------------------------------
extern "C" void kernel_launch(void* const* d_in, const int* in_sizes, int n_in,
                              void* d_out, int out_size)
{
    const float* x     = (const float*)d_in[0];
    const float* Wqkv  = (const float*)d_in[1];
    const float* bqkv  = (const float*)d_in[2];
    const float* Wproj = (const float*)d_in[3];
    const float* bproj = (const float*)d_in[4];
    float* out = (float*)d_out;

    cudaFuncSetAttribute(attn3_kernel,
                         cudaFuncAttributeMaxDynamicSharedMemorySize,
                         ATTN_SMEM_BYTES);

    gemm_qkv_kernel<<<dim3(NQKV / 128, M_TOT / 128), 256>>>(x, Wqkv, bqkv);
    attn3_kernel<<<dim3(BSZ * NH, SEQ / BQ), 256, ATTN_SMEM_BYTES>>>();
    gemm_proj_kernel<<<dim3(DIM / 128, M_TOT / 128), 256>>>(Wproj, bproj, out);
}

// round 7
// speedup vs baseline: 2.0273x; 1.1210x over previous
#include <cuda_runtime.h>
#include <cstdint>

#define BSZ 2
#define SEQ 2048
#define DIM 768
#define NH 12
#define HD 64
#define M_TOT (BSZ * SEQ)   // 4096
#define NQKV (3 * DIM)      // 2304

// Scratch (allocation-free rule: __device__ globals)
__device__ float g_qT[(size_t)BSZ * NH * HD * SEQ];   // k-major [bh][d][s]
__device__ float g_kT[(size_t)BSZ * NH * HD * SEQ];   // k-major [bh][d][s]
__device__ float g_v [(size_t)BSZ * NH * SEQ * HD];   // [bh][s][d]
__device__ float g_attn[(size_t)BSZ * SEQ * DIM];

__device__ __forceinline__ float neg_inf() { return __int_as_float(0xff800000u); }

// ---- packed f32x2 helpers (Blackwell FFMA2 path) ----
typedef unsigned long long u64b;
__device__ __forceinline__ u64b pk2(float x, float y) {
    u64b r; asm("mov.b64 %0, {%1, %2};" : "=l"(r) : "f"(x), "f"(y)); return r;
}
__device__ __forceinline__ u64b dup2(float x) { return pk2(x, x); }
__device__ __forceinline__ void upk2(u64b v, float& x, float& y) {
    asm("mov.b64 {%0, %1}, %2;" : "=f"(x), "=f"(y) : "l"(v));
}
__device__ __forceinline__ void fma2(u64b& c, u64b a, u64b b) {
    asm("fma.rn.f32x2 %0, %1, %2, %0;" : "+l"(c) : "l"(a), "l"(b));
}
__device__ __forceinline__ u64b mul2(u64b a, u64b b) {
    u64b r; asm("mul.rn.f32x2 %0, %1, %2;" : "=l"(r) : "l"(a), "l"(b)); return r;
}

// ---------------------------------------------------------------------------
// FFMA2 GEMM: 256x128 block, 256 threads, 16x8 micro-tile (f32x2 row pairs).
// As [2][16][260] k-major (m contiguous), Bs [2][16][132].
// MODE 0: A = x argument; epilogue scatters Q/K k-major, V token-major (+bias)
// MODE 1: A = g_attn DEVICE SYMBOL (fix: never pass __device__ global from
//         host); epilogue writes out = C + bias row-major.
// ---------------------------------------------------------------------------
#define M2 256
#define KS 16
#define AS_LDG 260
#define BS_LDG 132
#define A_ST (KS * AS_LDG)                       // 4160 floats
#define B_ST (KS * BS_LDG)                       // 2112 floats
#define GEMM_SMEM_BYTES ((A_ST + B_ST) * 2 * 4)  // 50176
#define NKT (DIM / KS)                           // 48

template <int N, int MODE>
__global__ void __launch_bounds__(256) gemm_f2_kernel(
    const float* __restrict__ Ain, const float* __restrict__ W,
    const float* __restrict__ bias, float* __restrict__ out)
{
    extern __shared__ float sg[];
    float* As = sg;                 // [2][KS][AS_LDG]
    float* Bs = sg + 2 * A_ST;      // [2][KS][BS_LDG]

    // CRITICAL: device-symbol read for MODE 1 (host cannot pass g_attn).
    const float* A = (MODE == 1) ? (const float*)g_attn : Ain;

    const int tid = threadIdx.x;
    const int tx = tid & 15;        // col group: cols tx*8 .. +7
    const int ty = tid >> 4;        // row group: rows ty*16 .. +15
    const int m0 = blockIdx.y * M2;
    const int n0 = blockIdx.x * 128;

    // loaders: A row per thread; B row ty, two f4 per thread
    const float* Ag = A + (size_t)(m0 + tid) * DIM;
    const float* Wg = W + (size_t)ty * N + n0;

    u64b acc2[8][8];
#pragma unroll
    for (int i = 0; i < 8; ++i)
#pragma unroll
        for (int j = 0; j < 8; ++j) acc2[i][j] = 0ull;

    float4 pa[4];
    float4 pb[2];
#pragma unroll
    for (int q = 0; q < 4; ++q) pa[q] = *(const float4*)&Ag[q * 4];
    pb[0] = *(const float4*)&Wg[tx * 4];
    pb[1] = *(const float4*)&Wg[64 + tx * 4];

    for (int kt = 0; kt < NKT; ++kt) {
        float* Ab = As + (kt & 1) * A_ST;
        float* Bb = Bs + (kt & 1) * B_ST;
        // stage stores (A transposed to k-major)
#pragma unroll
        for (int q = 0; q < 4; ++q) {
            Ab[(q * 4 + 0) * AS_LDG + tid] = pa[q].x;
            Ab[(q * 4 + 1) * AS_LDG + tid] = pa[q].y;
            Ab[(q * 4 + 2) * AS_LDG + tid] = pa[q].z;
            Ab[(q * 4 + 3) * AS_LDG + tid] = pa[q].w;
        }
        *(float4*)&Bb[ty * BS_LDG + tx * 4] = pb[0];
        *(float4*)&Bb[ty * BS_LDG + 64 + tx * 4] = pb[1];
        __syncthreads();

        // prefetch next stage
        if (kt + 1 < NKT) {
            const int ko = (kt + 1) * KS;
#pragma unroll
            for (int q = 0; q < 4; ++q) pa[q] = *(const float4*)&Ag[ko + q * 4];
            pb[0] = *(const float4*)&Wg[(size_t)ko * N + tx * 4];
            pb[1] = *(const float4*)&Wg[(size_t)ko * N + 64 + tx * 4];
        }

        // compute
#pragma unroll
        for (int kk = 0; kk < KS; ++kk) {
            u64b ra2[8];
#pragma unroll
            for (int q = 0; q < 4; ++q) {
                const ulonglong2 r = *(const ulonglong2*)&Ab[kk * AS_LDG + ty * 16 + q * 4];
                ra2[q * 2] = r.x;
                ra2[q * 2 + 1] = r.y;
            }
            const float4 b0 = *(const float4*)&Bb[kk * BS_LDG + tx * 8];
            const float4 b1 = *(const float4*)&Bb[kk * BS_LDG + tx * 8 + 4];
            u64b bb[8];
            bb[0] = dup2(b0.x); bb[1] = dup2(b0.y); bb[2] = dup2(b0.z); bb[3] = dup2(b0.w);
            bb[4] = dup2(b1.x); bb[5] = dup2(b1.y); bb[6] = dup2(b1.z); bb[7] = dup2(b1.w);
#pragma unroll
            for (int i2 = 0; i2 < 8; ++i2)
#pragma unroll
                for (int j = 0; j < 8; ++j)
                    fma2(acc2[i2][j], ra2[i2], bb[j]);
        }
        __syncthreads();
    }

    // unpack accumulators: rows 2*i2, 2*i2+1
    float cr[16][8];
#pragma unroll
    for (int i2 = 0; i2 < 8; ++i2)
#pragma unroll
        for (int j = 0; j < 8; ++j)
            upk2(acc2[i2][j], cr[2 * i2][j], cr[2 * i2 + 1][j]);

    const int bb_ = m0 >> 11;
    const int sbase = (m0 & (SEQ - 1)) + ty * 16;

    if (MODE == 1) {
#pragma unroll
        for (int i = 0; i < 16; ++i) {
            const int row = m0 + ty * 16 + i;
#pragma unroll
            for (int j4 = 0; j4 < 2; ++j4) {
                const int n = n0 + tx * 8 + j4 * 4;
                float4 w;
                w.x = cr[i][j4 * 4 + 0] + bias[n + 0];
                w.y = cr[i][j4 * 4 + 1] + bias[n + 1];
                w.z = cr[i][j4 * 4 + 2] + bias[n + 2];
                w.w = cr[i][j4 * 4 + 3] + bias[n + 3];
                *(float4*)&out[(size_t)row * DIM + n] = w;
            }
        }
    } else {
        const int which = n0 / DIM;
        if (which == 2) {
            // V: token-major, f4 along d
#pragma unroll
            for (int i = 0; i < 16; ++i) {
                const int ss = sbase + i;
#pragma unroll
                for (int j4 = 0; j4 < 2; ++j4) {
                    const int n = n0 + tx * 8 + j4 * 4;
                    const int rem = n - 2 * DIM;
                    const int h = rem >> 6, d = rem & 63;
                    float4 w;
                    w.x = cr[i][j4 * 4 + 0] + bias[n + 0];
                    w.y = cr[i][j4 * 4 + 1] + bias[n + 1];
                    w.z = cr[i][j4 * 4 + 2] + bias[n + 2];
                    w.w = cr[i][j4 * 4 + 3] + bias[n + 3];
                    *(float4*)&g_v[(((size_t)bb_ * NH + h) * SEQ + ss) * HD + d] = w;
                }
            }
        } else {
            // Q/K: k-major [bh][d][s], f4 along s (16 consecutive rows/thread)
            float* dst = (which == 0) ? g_qT : g_kT;
#pragma unroll
            for (int j = 0; j < 8; ++j) {
                const int n = n0 + tx * 8 + j;
                const int rem = n - which * DIM;
                const int h = rem >> 6, d = rem & 63;
                const float bn = bias[n];
                float* p = &dst[((size_t)(bb_ * NH + h) * HD + d) * SEQ + sbase];
#pragma unroll
                for (int gq = 0; gq < 4; ++gq) {
                    float4 w;
                    w.x = cr[gq * 4 + 0][j] + bn;
                    w.y = cr[gq * 4 + 1][j] + bn;
                    w.z = cr[gq * 4 + 2][j] + bn;
                    w.w = cr[gq * 4 + 3][j] + bn;
                    *(float4*)&p[gq * 4] = w;
                }
            }
        }
    }
}

// ---------------------------------------------------------------------------
// Flash attention (fp32, causal) with FFMA2 inner loops.
// Same structure/layouts as the proven 823us kernel.
// ---------------------------------------------------------------------------
#define BQ 128
#define BKK 128
#define QK_LD 132
#define VS_LD 68
#define PS_LD 132
#define ATTN_SMEM_FLOATS (64 * QK_LD + 64 * QK_LD + BKK * VS_LD + BQ * PS_LD)
#define ATTN_SMEM_BYTES (ATTN_SMEM_FLOATS * 4)

__global__ void __launch_bounds__(256, 1) attn4_kernel()
{
    extern __shared__ float sm[];
    float* Qs = sm;                       // [64][132] k-major: Qs[k][m]
    float* Ks = Qs + 64 * QK_LD;          // [64][132] k-major: Ks[k][j]
    float* Vs = Ks + 64 * QK_LD;          // [128][68]: Vs[j][d]
    float* Ps = Vs + BKK * VS_LD;         // [128][132]: Ps[r][j]

    const int bh = blockIdx.x;
    const int qi = (gridDim.y - 1) - blockIdx.y;   // heavy tiles first
    const int q0 = qi * BQ;

    const float* QTb = g_qT + (size_t)bh * HD * SEQ;
    const float* KTb = g_kT + (size_t)bh * HD * SEQ;
    const float* Vb  = g_v  + (size_t)bh * SEQ * HD;

    const int tid = threadIdx.x;
    const int ty = tid >> 4;
    const int tx = tid & 15;
    const int r0 = ty * 8;

#pragma unroll
    for (int t = 0; t < 8; ++t) {
        const int f = tid + t * 256;
        const int k = f >> 5;
        const int c4 = (f & 31) << 2;
        *(float4*)&Qs[k * QK_LD + c4] = *(const float4*)&QTb[(size_t)k * SEQ + q0 + c4];
    }

    u64b o2[8][2];   // output d-pairs: (o[i][0],o[i][1]), (o[i][2],o[i][3])
#pragma unroll
    for (int i = 0; i < 8; ++i) { o2[i][0] = 0ull; o2[i][1] = 0ull; }
    float mrow[8], lrow[8];
#pragma unroll
    for (int i = 0; i < 8; ++i) { mrow[i] = neg_inf(); lrow[i] = 0.f; }

    for (int kt = 0; kt <= qi; ++kt) {
        __syncthreads();

#pragma unroll
        for (int t = 0; t < 8; ++t) {
            const int f = tid + t * 256;
            const int k = f >> 5;
            const int c4 = (f & 31) << 2;
            *(float4*)&Ks[k * QK_LD + c4] =
                *(const float4*)&KTb[(size_t)k * SEQ + kt * BKK + c4];
        }
#pragma unroll
        for (int t = 0; t < 8; ++t) {
            const int f = tid + t * 256;
            const int j = f >> 4;
            const int d4 = (f & 15) << 2;
            *(float4*)&Vs[j * VS_LD + d4] =
                *(const float4*)&Vb[((size_t)kt * BKK + j) * HD + d4];
        }
        __syncthreads();

        // ---- S = Q^T . K : FFMA2 over j-pairs ----
        u64b sv2[8][4];
#pragma unroll
        for (int i = 0; i < 8; ++i)
#pragma unroll
            for (int j2 = 0; j2 < 4; ++j2) sv2[i][j2] = 0ull;

#pragma unroll 8
        for (int k = 0; k < HD; ++k) {
            float qv[8];
            *(float4*)&qv[0] = *(const float4*)&Qs[k * QK_LD + r0];
            *(float4*)&qv[4] = *(const float4*)&Qs[k * QK_LD + r0 + 4];
            const ulonglong2 kA = *(const ulonglong2*)&Ks[k * QK_LD + tx * 8];
            const ulonglong2 kB = *(const ulonglong2*)&Ks[k * QK_LD + tx * 8 + 4];
            u64b kv2[4];
            kv2[0] = kA.x; kv2[1] = kA.y; kv2[2] = kB.x; kv2[3] = kB.y;
#pragma unroll
            for (int i = 0; i < 8; ++i) {
                const u64b qd = dup2(qv[i]);
                fma2(sv2[i][0], qd, kv2[0]);
                fma2(sv2[i][1], qd, kv2[1]);
                fma2(sv2[i][2], qd, kv2[2]);
                fma2(sv2[i][3], qd, kv2[3]);
            }
        }

        // ---- softmax ----
        const bool diag = (kt == qi);
#pragma unroll
        for (int i = 0; i < 8; ++i) {
            float s[8];
#pragma unroll
            for (int j2 = 0; j2 < 4; ++j2)
                upk2(sv2[i][j2], s[2 * j2], s[2 * j2 + 1]);
#pragma unroll
            for (int j = 0; j < 8; ++j) s[j] *= 0.125f;
            if (diag) {
                const int rl = r0 + i;
#pragma unroll
                for (int j = 0; j < 8; ++j)
                    if (tx * 8 + j > rl) s[j] = neg_inf();
            }
            float mt = s[0];
#pragma unroll
            for (int j = 1; j < 8; ++j) mt = fmaxf(mt, s[j]);
            mt = fmaxf(mt, __shfl_xor_sync(0xffffffffu, mt, 1));
            mt = fmaxf(mt, __shfl_xor_sync(0xffffffffu, mt, 2));
            mt = fmaxf(mt, __shfl_xor_sync(0xffffffffu, mt, 4));
            mt = fmaxf(mt, __shfl_xor_sync(0xffffffffu, mt, 8));
            const float mn = fmaxf(mrow[i], mt);
            const float corr = __expf(mrow[i] - mn);
            float rs = 0.f;
#pragma unroll
            for (int j = 0; j < 8; ++j) {
                s[j] = __expf(s[j] - mn);
                rs += s[j];
            }
            rs += __shfl_xor_sync(0xffffffffu, rs, 1);
            rs += __shfl_xor_sync(0xffffffffu, rs, 2);
            rs += __shfl_xor_sync(0xffffffffu, rs, 4);
            rs += __shfl_xor_sync(0xffffffffu, rs, 8);
            lrow[i] = lrow[i] * corr + rs;
            mrow[i] = mn;
            const u64b cd = dup2(corr);
            o2[i][0] = mul2(o2[i][0], cd);
            o2[i][1] = mul2(o2[i][1], cd);
            *(float4*)&Ps[(r0 + i) * PS_LD + tx * 8] =
                make_float4(s[0], s[1], s[2], s[3]);
            *(float4*)&Ps[(r0 + i) * PS_LD + tx * 8 + 4] =
                make_float4(s[4], s[5], s[6], s[7]);
        }
        __syncwarp();

        // ---- O += P @ V : FFMA2 over d-pairs ----
#pragma unroll 2
        for (int j4 = 0; j4 < BKK / 4; ++j4) {
            u64b vv2[4][2];
#pragma unroll
            for (int e = 0; e < 4; ++e) {
                const ulonglong2 ve = *(const ulonglong2*)&Vs[(j4 * 4 + e) * VS_LD + tx * 4];
                vv2[e][0] = ve.x;
                vv2[e][1] = ve.y;
            }
#pragma unroll
            for (int i = 0; i < 8; ++i) {
                const float4 pp = *(const float4*)&Ps[(r0 + i) * PS_LD + j4 * 4];
                u64b pd;
                pd = dup2(pp.x); fma2(o2[i][0], pd, vv2[0][0]); fma2(o2[i][1], pd, vv2[0][1]);
                pd = dup2(pp.y); fma2(o2[i][0], pd, vv2[1][0]); fma2(o2[i][1], pd, vv2[1][1]);
                pd = dup2(pp.z); fma2(o2[i][0], pd, vv2[2][0]); fma2(o2[i][1], pd, vv2[2][1]);
                pd = dup2(pp.w); fma2(o2[i][0], pd, vv2[3][0]); fma2(o2[i][1], pd, vv2[3][1]);
            }
        }
    }

    const int bb = bh / NH;
    const int h = bh - bb * NH;
#pragma unroll
    for (int i = 0; i < 8; ++i) {
        const float inv = 1.f / lrow[i];
        float o0, o1, o2v, o3;
        upk2(o2[i][0], o0, o1);
        upk2(o2[i][1], o2v, o3);
        float4 w;
        w.x = o0 * inv; w.y = o1 * inv; w.z = o2v * inv; w.w = o3 * inv;
        *(float4*)&g_attn[((size_t)(bb * SEQ) + q0 + r0 + i) * DIM + h * HD + tx * 4] = w;
    }
}

// ---------------------------------------------------------------------------
extern "C" void kernel_launch(void* const* d_in, const int* in_sizes, int n_in,
                              void* d_out, int out_size)
{
    const float* x     = (const float*)d_in[0];
    const float* Wqkv  = (const float*)d_in[1];
    const float* bqkv  = (const float*)d_in[2];
    const float* Wproj = (const float*)d_in[3];
    const float* bproj = (const float*)d_in[4];
    float* out = (float*)d_out;

    cudaFuncSetAttribute(gemm_f2_kernel<NQKV, 0>,
                         cudaFuncAttributeMaxDynamicSharedMemorySize, GEMM_SMEM_BYTES);
    cudaFuncSetAttribute(gemm_f2_kernel<DIM, 1>,
                         cudaFuncAttributeMaxDynamicSharedMemorySize, GEMM_SMEM_BYTES);
    cudaFuncSetAttribute(attn4_kernel,
                         cudaFuncAttributeMaxDynamicSharedMemorySize, ATTN_SMEM_BYTES);

    gemm_f2_kernel<NQKV, 0><<<dim3(NQKV / 128, M_TOT / M2), 256, GEMM_SMEM_BYTES>>>(
        x, Wqkv, bqkv, nullptr);
    attn4_kernel<<<dim3(BSZ * NH, SEQ / BQ), 256, ATTN_SMEM_BYTES>>>();
    gemm_f2_kernel<DIM, 1><<<dim3(DIM / 128, M_TOT / M2), 256, GEMM_SMEM_BYTES>>>(
        nullptr /* A read from g_attn device symbol */, Wproj, bproj, out);
}

// round 8
// speedup vs baseline: 2.5761x; 1.2707x over previous
#include <cuda_runtime.h>
#include <cuda_bf16.h>
#include <cstdint>

#define BSZ 2
#define SEQ 2048
#define DIM 768
#define NH 12
#define HD 64
#define M_TOT (BSZ * SEQ)   // 4096
#define NQKV (3 * DIM)      // 2304

// Scratch (allocation-free rule: __device__ globals)
__device__ float g_qT[(size_t)BSZ * NH * HD * SEQ];   // k-major [bh][d][s]
__device__ float g_kT[(size_t)BSZ * NH * HD * SEQ];   // k-major [bh][d][s]
__device__ float g_v [(size_t)BSZ * NH * SEQ * HD];   // [bh][s][d]
__device__ float g_attn[(size_t)BSZ * SEQ * DIM];

__device__ __forceinline__ float neg_inf() { return __int_as_float(0xff800000u); }

// ---- packed f32x2 helpers (FFMA2 path, used by attention) ----
typedef unsigned long long u64b;
__device__ __forceinline__ u64b pk2(float x, float y) {
    u64b r; asm("mov.b64 %0, {%1, %2};" : "=l"(r) : "f"(x), "f"(y)); return r;
}
__device__ __forceinline__ u64b dup2(float x) { return pk2(x, x); }
__device__ __forceinline__ void upk2(u64b v, float& x, float& y) {
    asm("mov.b64 {%0, %1}, %2;" : "=f"(x), "=f"(y) : "l"(v));
}
__device__ __forceinline__ void fma2(u64b& c, u64b a, u64b b) {
    asm("fma.rn.f32x2 %0, %1, %2, %0;" : "+l"(c) : "l"(a), "l"(b));
}
__device__ __forceinline__ u64b mul2(u64b a, u64b b) {
    u64b r; asm("mul.rn.f32x2 %0, %1, %2;" : "=l"(r) : "l"(a), "l"(b)); return r;
}

// ---- bf16 split helpers (mma path) ----
__device__ __forceinline__ void split2(float x0, float x1, uint32_t& hi, uint32_t& lo) {
    __nv_bfloat162 h, l;
    h.x = __float2bfloat16_rn(x0);
    h.y = __float2bfloat16_rn(x1);
    l.x = __float2bfloat16_rn(x0 - __bfloat162float(h.x));
    l.y = __float2bfloat16_rn(x1 - __bfloat162float(h.y));
    hi = *(uint32_t*)&h;
    lo = *(uint32_t*)&l;
}

__device__ __forceinline__ void mma16(float* c,
    uint32_t a0, uint32_t a1, uint32_t a2, uint32_t a3,
    uint32_t b0, uint32_t b1)
{
    asm volatile(
        "mma.sync.aligned.m16n8k16.row.col.f32.bf16.bf16.f32 "
        "{%0,%1,%2,%3}, {%4,%5,%6,%7}, {%8,%9}, {%0,%1,%2,%3};"
        : "+f"(c[0]), "+f"(c[1]), "+f"(c[2]), "+f"(c[3])
        : "r"(a0), "r"(a1), "r"(a2), "r"(a3), "r"(b0), "r"(b1));
}

// ---------------------------------------------------------------------------
// bf16x3 tensor-core GEMM: C[128,128] block, 8 warps (2m x 4n), warp 64x32.
// K-stage 32. A hi/lo bf16 [128][40]; W hi/lo pair-interleaved u32 [16][136].
// MODE 0: A = arg; QKV epilogue (Q/K k-major scatter, V token-major, +bias)
// MODE 1: A = g_attn device symbol; out = C + bias row-major.
// ---------------------------------------------------------------------------
#define ALD2 20      // u32 per A row (40 bf16)
#define WLD2 136     // u32 per W k-pair row
#define A_U32 (128 * ALD2)   // 2560
#define W_U32 (16 * WLD2)    // 2176
#define GEMM_SMEM_BYTES ((2 * A_U32 + 2 * W_U32) * 4)   // 37888
#define NKT (DIM / 32)       // 24

template <int N, int MODE>
__global__ void __launch_bounds__(256) gemm_bf3_kernel(
    const float* __restrict__ Ain, const float* __restrict__ W,
    const float* __restrict__ bias, float* __restrict__ out)
{
    extern __shared__ uint32_t smu[];
    uint32_t* ahi = smu;
    uint32_t* alo = ahi + A_U32;
    uint32_t* whi = alo + A_U32;
    uint32_t* wlo = whi + W_U32;

    // CRITICAL: device-symbol read for MODE 1 (host cannot pass g_attn).
    const float* A = (MODE == 1) ? (const float*)g_attn : Ain;

    const int tid = threadIdx.x;
    const int lane = tid & 31;
    const int warp = tid >> 5;
    const int g = lane >> 2;
    const int tig = lane & 3;
    const int wm0 = (warp >> 2) * 64;
    const int wn0 = (warp & 3) * 32;
    const int m0 = blockIdx.y * 128;
    const int n0 = blockIdx.x * 128;

    // fill-phase mappings
    const int fa_m = tid >> 1;                 // 0..127
    const int fa_c = (tid & 1) * 16;           // k base 0 or 16
    const int fw_k2 = tid >> 4;                // 0..15
    const int fw_n = (tid & 15) * 8;           // 0..120

    const float* Ag = A + (size_t)(m0 + fa_m) * DIM + fa_c;
    const float* Wg0 = W + (size_t)(2 * fw_k2) * N + n0 + fw_n;
    const float* Wg1 = Wg0 + N;

    float c[4][4][4];
#pragma unroll
    for (int ti = 0; ti < 4; ++ti)
#pragma unroll
        for (int tj = 0; tj < 4; ++tj)
#pragma unroll
            for (int e = 0; e < 4; ++e) c[ti][tj][e] = 0.f;

    float4 pfa[4], pfw[4];
#pragma unroll
    for (int q = 0; q < 4; ++q) {
        pfa[q] = *(const float4*)&Ag[q * 4];
        pfw[q] = (q < 2) ? *(const float4*)&Wg0[q * 4] : *(const float4*)&Wg1[(q - 2) * 4];
    }

    for (int kt = 0; kt < NKT; ++kt) {
        // ---- convert + store stage to smem ----
#pragma unroll
        for (int q = 0; q < 4; ++q) {
            uint32_t h0, l0, h1, l1;
            split2(pfa[q].x, pfa[q].y, h0, l0);
            split2(pfa[q].z, pfa[q].w, h1, l1);
            const int idx = fa_m * ALD2 + (fa_c + q * 4) / 2;
            ahi[idx] = h0; ahi[idx + 1] = h1;
            alo[idx] = l0; alo[idx + 1] = l1;
        }
        {
            const float* r0 = (const float*)&pfw[0];   // W[k][n..n+7]
            const float* r1 = (const float*)&pfw[2];   // W[k+1][n..n+7]
            uint32_t wh[8], wl[8];
#pragma unroll
            for (int cc = 0; cc < 8; ++cc)
                split2(r0[cc], r1[cc], wh[cc], wl[cc]);
            const int idx = fw_k2 * WLD2 + fw_n;
#pragma unroll
            for (int cc = 0; cc < 8; ++cc) {
                whi[idx + cc] = wh[cc];
                wlo[idx + cc] = wl[cc];
            }
        }
        __syncthreads();

        // ---- prefetch next stage ----
        if (kt + 1 < NKT) {
            const int ko = (kt + 1) * 32;
#pragma unroll
            for (int q = 0; q < 4; ++q) {
                pfa[q] = *(const float4*)&Ag[ko + q * 4];
                pfw[q] = (q < 2) ? *(const float4*)&Wg0[(size_t)ko * N + q * 4]
                                 : *(const float4*)&Wg1[(size_t)ko * N + (q - 2) * 4];
            }
        }

        // ---- compute: two k16 steps, 3 passes each ----
#pragma unroll
        for (int k16 = 0; k16 < 2; ++k16) {
            const int ac = k16 * 8 + tig;       // u32 col in A rows
            const int wr = k16 * 8 + tig;       // k2 row in W tiles
            uint32_t Ah[4][4], Al[4][4], Bh[4][2], Bl[4][2];
#pragma unroll
            for (int ti = 0; ti < 4; ++ti) {
                const int r = wm0 + 16 * ti + g;
                Ah[ti][0] = ahi[r * ALD2 + ac];
                Ah[ti][1] = ahi[(r + 8) * ALD2 + ac];
                Ah[ti][2] = ahi[r * ALD2 + ac + 4];
                Ah[ti][3] = ahi[(r + 8) * ALD2 + ac + 4];
            }
#pragma unroll
            for (int tj = 0; tj < 4; ++tj) {
                const int nn = wn0 + 8 * tj + g;
                Bh[tj][0] = whi[wr * WLD2 + nn];
                Bh[tj][1] = whi[(wr + 4) * WLD2 + nn];
            }
#pragma unroll
            for (int ti = 0; ti < 4; ++ti)
#pragma unroll
                for (int tj = 0; tj < 4; ++tj)
                    mma16(c[ti][tj], Ah[ti][0], Ah[ti][1], Ah[ti][2], Ah[ti][3],
                          Bh[tj][0], Bh[tj][1]);
#pragma unroll
            for (int ti = 0; ti < 4; ++ti) {
                const int r = wm0 + 16 * ti + g;
                Al[ti][0] = alo[r * ALD2 + ac];
                Al[ti][1] = alo[(r + 8) * ALD2 + ac];
                Al[ti][2] = alo[r * ALD2 + ac + 4];
                Al[ti][3] = alo[(r + 8) * ALD2 + ac + 4];
            }
#pragma unroll
            for (int ti = 0; ti < 4; ++ti)
#pragma unroll
                for (int tj = 0; tj < 4; ++tj)
                    mma16(c[ti][tj], Al[ti][0], Al[ti][1], Al[ti][2], Al[ti][3],
                          Bh[tj][0], Bh[tj][1]);
#pragma unroll
            for (int tj = 0; tj < 4; ++tj) {
                const int nn = wn0 + 8 * tj + g;
                Bl[tj][0] = wlo[wr * WLD2 + nn];
                Bl[tj][1] = wlo[(wr + 4) * WLD2 + nn];
            }
#pragma unroll
            for (int ti = 0; ti < 4; ++ti)
#pragma unroll
                for (int tj = 0; tj < 4; ++tj)
                    mma16(c[ti][tj], Ah[ti][0], Ah[ti][1], Ah[ti][2], Ah[ti][3],
                          Bl[tj][0], Bl[tj][1]);
        }
        __syncthreads();
    }

    // ---- epilogue: direct fragment stores ----
    const int bb = m0 >> 11;
    const int which = n0 / DIM;

#pragma unroll
    for (int ti = 0; ti < 4; ++ti) {
        const int m = m0 + wm0 + 16 * ti + g;     // rows m, m+8
        const int s = m & (SEQ - 1);
#pragma unroll
        for (int tj = 0; tj < 4; ++tj) {
            const int n = n0 + wn0 + 8 * tj + 2 * tig;
            const float b0 = __ldg(&bias[n]);
            const float b1 = __ldg(&bias[n + 1]);
            if (MODE == 1) {
                float2 v0, v1;
                v0.x = c[ti][tj][0] + b0; v0.y = c[ti][tj][1] + b1;
                v1.x = c[ti][tj][2] + b0; v1.y = c[ti][tj][3] + b1;
                *(float2*)&out[(size_t)m * DIM + n] = v0;
                *(float2*)&out[(size_t)(m + 8) * DIM + n] = v1;
            } else {
                const int rem = n - which * DIM;
                const int h = rem >> 6, d = rem & 63;
                if (which == 2) {
                    float* base = g_v + ((size_t)(bb * NH + h) * SEQ) * HD + d;
                    float2 v0, v1;
                    v0.x = c[ti][tj][0] + b0; v0.y = c[ti][tj][1] + b1;
                    v1.x = c[ti][tj][2] + b0; v1.y = c[ti][tj][3] + b1;
                    *(float2*)&base[(size_t)s * HD] = v0;
                    *(float2*)&base[(size_t)(s + 8) * HD] = v1;
                } else {
                    float* dst = (which == 0) ? g_qT : g_kT;
                    float* base = dst + ((size_t)(bb * NH + h) * HD + d) * SEQ;
                    base[s]           = c[ti][tj][0] + b0;
                    base[SEQ + s]     = c[ti][tj][1] + b1;
                    base[s + 8]       = c[ti][tj][2] + b0;
                    base[SEQ + s + 8] = c[ti][tj][3] + b1;
                }
            }
        }
    }
}

// ---------------------------------------------------------------------------
// Flash attention (fp32, causal) with FFMA2 inner loops — R7 passing version.
// ---------------------------------------------------------------------------
#define BQ 128
#define BKK 128
#define QK_LD 132
#define VS_LD 68
#define PS_LD 132
#define ATTN_SMEM_FLOATS (64 * QK_LD + 64 * QK_LD + BKK * VS_LD + BQ * PS_LD)
#define ATTN_SMEM_BYTES (ATTN_SMEM_FLOATS * 4)

__global__ void __launch_bounds__(256, 1) attn4_kernel()
{
    extern __shared__ float sm[];
    float* Qs = sm;                       // [64][132] k-major: Qs[k][m]
    float* Ks = Qs + 64 * QK_LD;          // [64][132] k-major: Ks[k][j]
    float* Vs = Ks + 64 * QK_LD;          // [128][68]: Vs[j][d]
    float* Ps = Vs + BKK * VS_LD;         // [128][132]: Ps[r][j]

    const int bh = blockIdx.x;
    const int qi = (gridDim.y - 1) - blockIdx.y;   // heavy tiles first
    const int q0 = qi * BQ;

    const float* QTb = g_qT + (size_t)bh * HD * SEQ;
    const float* KTb = g_kT + (size_t)bh * HD * SEQ;
    const float* Vb  = g_v  + (size_t)bh * SEQ * HD;

    const int tid = threadIdx.x;
    const int ty = tid >> 4;
    const int tx = tid & 15;
    const int r0 = ty * 8;

#pragma unroll
    for (int t = 0; t < 8; ++t) {
        const int f = tid + t * 256;
        const int k = f >> 5;
        const int c4 = (f & 31) << 2;
        *(float4*)&Qs[k * QK_LD + c4] = *(const float4*)&QTb[(size_t)k * SEQ + q0 + c4];
    }

    u64b o2[8][2];
#pragma unroll
    for (int i = 0; i < 8; ++i) { o2[i][0] = 0ull; o2[i][1] = 0ull; }
    float mrow[8], lrow[8];
#pragma unroll
    for (int i = 0; i < 8; ++i) { mrow[i] = neg_inf(); lrow[i] = 0.f; }

    for (int kt = 0; kt <= qi; ++kt) {
        __syncthreads();

#pragma unroll
        for (int t = 0; t < 8; ++t) {
            const int f = tid + t * 256;
            const int k = f >> 5;
            const int c4 = (f & 31) << 2;
            *(float4*)&Ks[k * QK_LD + c4] =
                *(const float4*)&KTb[(size_t)k * SEQ + kt * BKK + c4];
        }
#pragma unroll
        for (int t = 0; t < 8; ++t) {
            const int f = tid + t * 256;
            const int j = f >> 4;
            const int d4 = (f & 15) << 2;
            *(float4*)&Vs[j * VS_LD + d4] =
                *(const float4*)&Vb[((size_t)kt * BKK + j) * HD + d4];
        }
        __syncthreads();

        // ---- S = Q^T . K : FFMA2 over j-pairs ----
        u64b sv2[8][4];
#pragma unroll
        for (int i = 0; i < 8; ++i)
#pragma unroll
            for (int j2 = 0; j2 < 4; ++j2) sv2[i][j2] = 0ull;

#pragma unroll 8
        for (int k = 0; k < HD; ++k) {
            float qv[8];
            *(float4*)&qv[0] = *(const float4*)&Qs[k * QK_LD + r0];
            *(float4*)&qv[4] = *(const float4*)&Qs[k * QK_LD + r0 + 4];
            const ulonglong2 kA = *(const ulonglong2*)&Ks[k * QK_LD + tx * 8];
            const ulonglong2 kB = *(const ulonglong2*)&Ks[k * QK_LD + tx * 8 + 4];
            u64b kv2[4];
            kv2[0] = kA.x; kv2[1] = kA.y; kv2[2] = kB.x; kv2[3] = kB.y;
#pragma unroll
            for (int i = 0; i < 8; ++i) {
                const u64b qd = dup2(qv[i]);
                fma2(sv2[i][0], qd, kv2[0]);
                fma2(sv2[i][1], qd, kv2[1]);
                fma2(sv2[i][2], qd, kv2[2]);
                fma2(sv2[i][3], qd, kv2[3]);
            }
        }

        // ---- softmax ----
        const bool diag = (kt == qi);
#pragma unroll
        for (int i = 0; i < 8; ++i) {
            float s[8];
#pragma unroll
            for (int j2 = 0; j2 < 4; ++j2)
                upk2(sv2[i][j2], s[2 * j2], s[2 * j2 + 1]);
#pragma unroll
            for (int j = 0; j < 8; ++j) s[j] *= 0.125f;
            if (diag) {
                const int rl = r0 + i;
#pragma unroll
                for (int j = 0; j < 8; ++j)
                    if (tx * 8 + j > rl) s[j] = neg_inf();
            }
            float mt = s[0];
#pragma unroll
            for (int j = 1; j < 8; ++j) mt = fmaxf(mt, s[j]);
            mt = fmaxf(mt, __shfl_xor_sync(0xffffffffu, mt, 1));
            mt = fmaxf(mt, __shfl_xor_sync(0xffffffffu, mt, 2));
            mt = fmaxf(mt, __shfl_xor_sync(0xffffffffu, mt, 4));
            mt = fmaxf(mt, __shfl_xor_sync(0xffffffffu, mt, 8));
            const float mn = fmaxf(mrow[i], mt);
            const float corr = __expf(mrow[i] - mn);
            float rs = 0.f;
#pragma unroll
            for (int j = 0; j < 8; ++j) {
                s[j] = __expf(s[j] - mn);
                rs += s[j];
            }
            rs += __shfl_xor_sync(0xffffffffu, rs, 1);
            rs += __shfl_xor_sync(0xffffffffu, rs, 2);
            rs += __shfl_xor_sync(0xffffffffu, rs, 4);
            rs += __shfl_xor_sync(0xffffffffu, rs, 8);
            lrow[i] = lrow[i] * corr + rs;
            mrow[i] = mn;
            const u64b cd = dup2(corr);
            o2[i][0] = mul2(o2[i][0], cd);
            o2[i][1] = mul2(o2[i][1], cd);
            *(float4*)&Ps[(r0 + i) * PS_LD + tx * 8] =
                make_float4(s[0], s[1], s[2], s[3]);
            *(float4*)&Ps[(r0 + i) * PS_LD + tx * 8 + 4] =
                make_float4(s[4], s[5], s[6], s[7]);
        }
        __syncwarp();

        // ---- O += P @ V : FFMA2 over d-pairs ----
#pragma unroll 2
        for (int j4 = 0; j4 < BKK / 4; ++j4) {
            u64b vv2[4][2];
#pragma unroll
            for (int e = 0; e < 4; ++e) {
                const ulonglong2 ve = *(const ulonglong2*)&Vs[(j4 * 4 + e) * VS_LD + tx * 4];
                vv2[e][0] = ve.x;
                vv2[e][1] = ve.y;
            }
#pragma unroll
            for (int i = 0; i < 8; ++i) {
                const float4 pp = *(const float4*)&Ps[(r0 + i) * PS_LD + j4 * 4];
                u64b pd;
                pd = dup2(pp.x); fma2(o2[i][0], pd, vv2[0][0]); fma2(o2[i][1], pd, vv2[0][1]);
                pd = dup2(pp.y); fma2(o2[i][0], pd, vv2[1][0]); fma2(o2[i][1], pd, vv2[1][1]);
                pd = dup2(pp.z); fma2(o2[i][0], pd, vv2[2][0]); fma2(o2[i][1], pd, vv2[2][1]);
                pd = dup2(pp.w); fma2(o2[i][0], pd, vv2[3][0]); fma2(o2[i][1], pd, vv2[3][1]);
            }
        }
    }

    const int bb = bh / NH;
    const int h = bh - bb * NH;
#pragma unroll
    for (int i = 0; i < 8; ++i) {
        const float inv = 1.f / lrow[i];
        float o0, o1, o2v, o3;
        upk2(o2[i][0], o0, o1);
        upk2(o2[i][1], o2v, o3);
        float4 w;
        w.x = o0 * inv; w.y = o1 * inv; w.z = o2v * inv; w.w = o3 * inv;
        *(float4*)&g_attn[((size_t)(bb * SEQ) + q0 + r0 + i) * DIM + h * HD + tx * 4] = w;
    }
}

// ---------------------------------------------------------------------------
extern "C" void kernel_launch(void* const* d_in, const int* in_sizes, int n_in,
                              void* d_out, int out_size)
{
    const float* x     = (const float*)d_in[0];
    const float* Wqkv  = (const float*)d_in[1];
    const float* bqkv  = (const float*)d_in[2];
    const float* Wproj = (const float*)d_in[3];
    const float* bproj = (const float*)d_in[4];
    float* out = (float*)d_out;

    cudaFuncSetAttribute(attn4_kernel,
                         cudaFuncAttributeMaxDynamicSharedMemorySize, ATTN_SMEM_BYTES);

    gemm_bf3_kernel<NQKV, 0><<<dim3(NQKV / 128, M_TOT / 128), 256, GEMM_SMEM_BYTES>>>(
        x, Wqkv, bqkv, nullptr);
    attn4_kernel<<<dim3(BSZ * NH, SEQ / BQ), 256, ATTN_SMEM_BYTES>>>();
    gemm_bf3_kernel<DIM, 1><<<dim3(DIM / 128, M_TOT / 128), 256, GEMM_SMEM_BYTES>>>(
        nullptr /* A read from g_attn device symbol */, Wproj, bproj, out);
}

// round 9
// speedup vs baseline: 3.8806x; 1.5064x over previous
#include <cuda_runtime.h>
#include <cuda_bf16.h>
#include <cstdint>

#define BSZ 2
#define SEQ 2048
#define DIM 768
#define NH 12
#define HD 64
#define M_TOT (BSZ * SEQ)   // 4096
#define NQKV (3 * DIM)      // 2304

// Scratch (allocation-free rule: __device__ globals) — all token-major [bh][s][d]
__device__ float g_q[(size_t)BSZ * NH * SEQ * HD];
__device__ float g_k[(size_t)BSZ * NH * SEQ * HD];
__device__ float g_v[(size_t)BSZ * NH * SEQ * HD];
__device__ float g_attn[(size_t)BSZ * SEQ * DIM];

__device__ __forceinline__ float neg_inf() { return __int_as_float(0xff800000u); }

// ---- bf16 hi/lo split helpers ----
__device__ __forceinline__ void split2(float x0, float x1, uint32_t& hi, uint32_t& lo) {
    __nv_bfloat162 h, l;
    h.x = __float2bfloat16_rn(x0);
    h.y = __float2bfloat16_rn(x1);
    l.x = __float2bfloat16_rn(x0 - __bfloat162float(h.x));
    l.y = __float2bfloat16_rn(x1 - __bfloat162float(h.y));
    hi = *(uint32_t*)&h;
    lo = *(uint32_t*)&l;
}

__device__ __forceinline__ void mma16(float* c,
    uint32_t a0, uint32_t a1, uint32_t a2, uint32_t a3,
    uint32_t b0, uint32_t b1)
{
    asm volatile(
        "mma.sync.aligned.m16n8k16.row.col.f32.bf16.bf16.f32 "
        "{%0,%1,%2,%3}, {%4,%5,%6,%7}, {%8,%9}, {%0,%1,%2,%3};"
        : "+f"(c[0]), "+f"(c[1]), "+f"(c[2]), "+f"(c[3])
        : "r"(a0), "r"(a1), "r"(a2), "r"(a3), "r"(b0), "r"(b1));
}

// ---------------------------------------------------------------------------
// bf16x3 tensor-core GEMM (from R8, passing): C[128,128] block, 8 warps.
// MODE 0: A = arg; epilogue writes Q/K/V all token-major (+bias)
// MODE 1: A = g_attn device symbol; out = C + bias row-major.
// ---------------------------------------------------------------------------
#define ALD2 20
#define WLD2 136
#define A_U32 (128 * ALD2)
#define W_U32 (16 * WLD2)
#define GEMM_SMEM_BYTES ((2 * A_U32 + 2 * W_U32) * 4)
#define NKT (DIM / 32)

template <int N, int MODE>
__global__ void __launch_bounds__(256) gemm_bf3_kernel(
    const float* __restrict__ Ain, const float* __restrict__ W,
    const float* __restrict__ bias, float* __restrict__ out)
{
    extern __shared__ uint32_t smu[];
    uint32_t* ahi = smu;
    uint32_t* alo = ahi + A_U32;
    uint32_t* whi = alo + A_U32;
    uint32_t* wlo = whi + W_U32;

    const float* A = (MODE == 1) ? (const float*)g_attn : Ain;

    const int tid = threadIdx.x;
    const int lane = tid & 31;
    const int warp = tid >> 5;
    const int g = lane >> 2;
    const int tig = lane & 3;
    const int wm0 = (warp >> 2) * 64;
    const int wn0 = (warp & 3) * 32;
    const int m0 = blockIdx.y * 128;
    const int n0 = blockIdx.x * 128;

    const int fa_m = tid >> 1;
    const int fa_c = (tid & 1) * 16;
    const int fw_k2 = tid >> 4;
    const int fw_n = (tid & 15) * 8;

    const float* Ag = A + (size_t)(m0 + fa_m) * DIM + fa_c;
    const float* Wg0 = W + (size_t)(2 * fw_k2) * N + n0 + fw_n;
    const float* Wg1 = Wg0 + N;

    float c[4][4][4];
#pragma unroll
    for (int ti = 0; ti < 4; ++ti)
#pragma unroll
        for (int tj = 0; tj < 4; ++tj)
#pragma unroll
            for (int e = 0; e < 4; ++e) c[ti][tj][e] = 0.f;

    float4 pfa[4], pfw[4];
#pragma unroll
    for (int q = 0; q < 4; ++q) {
        pfa[q] = *(const float4*)&Ag[q * 4];
        pfw[q] = (q < 2) ? *(const float4*)&Wg0[q * 4] : *(const float4*)&Wg1[(q - 2) * 4];
    }

    for (int kt = 0; kt < NKT; ++kt) {
#pragma unroll
        for (int q = 0; q < 4; ++q) {
            uint32_t h0, l0, h1, l1;
            split2(pfa[q].x, pfa[q].y, h0, l0);
            split2(pfa[q].z, pfa[q].w, h1, l1);
            const int idx = fa_m * ALD2 + (fa_c + q * 4) / 2;
            ahi[idx] = h0; ahi[idx + 1] = h1;
            alo[idx] = l0; alo[idx + 1] = l1;
        }
        {
            const float* r0 = (const float*)&pfw[0];
            const float* r1 = (const float*)&pfw[2];
            uint32_t wh[8], wl[8];
#pragma unroll
            for (int cc = 0; cc < 8; ++cc)
                split2(r0[cc], r1[cc], wh[cc], wl[cc]);
            const int idx = fw_k2 * WLD2 + fw_n;
#pragma unroll
            for (int cc = 0; cc < 8; ++cc) {
                whi[idx + cc] = wh[cc];
                wlo[idx + cc] = wl[cc];
            }
        }
        __syncthreads();

        if (kt + 1 < NKT) {
            const int ko = (kt + 1) * 32;
#pragma unroll
            for (int q = 0; q < 4; ++q) {
                pfa[q] = *(const float4*)&Ag[ko + q * 4];
                pfw[q] = (q < 2) ? *(const float4*)&Wg0[(size_t)ko * N + q * 4]
                                 : *(const float4*)&Wg1[(size_t)ko * N + (q - 2) * 4];
            }
        }

#pragma unroll
        for (int k16 = 0; k16 < 2; ++k16) {
            const int ac = k16 * 8 + tig;
            const int wr = k16 * 8 + tig;
            uint32_t Ah[4][4], Al[4][4], Bh[4][2], Bl[4][2];
#pragma unroll
            for (int ti = 0; ti < 4; ++ti) {
                const int r = wm0 + 16 * ti + g;
                Ah[ti][0] = ahi[r * ALD2 + ac];
                Ah[ti][1] = ahi[(r + 8) * ALD2 + ac];
                Ah[ti][2] = ahi[r * ALD2 + ac + 4];
                Ah[ti][3] = ahi[(r + 8) * ALD2 + ac + 4];
            }
#pragma unroll
            for (int tj = 0; tj < 4; ++tj) {
                const int nn = wn0 + 8 * tj + g;
                Bh[tj][0] = whi[wr * WLD2 + nn];
                Bh[tj][1] = whi[(wr + 4) * WLD2 + nn];
            }
#pragma unroll
            for (int ti = 0; ti < 4; ++ti)
#pragma unroll
                for (int tj = 0; tj < 4; ++tj)
                    mma16(c[ti][tj], Ah[ti][0], Ah[ti][1], Ah[ti][2], Ah[ti][3],
                          Bh[tj][0], Bh[tj][1]);
#pragma unroll
            for (int ti = 0; ti < 4; ++ti) {
                const int r = wm0 + 16 * ti + g;
                Al[ti][0] = alo[r * ALD2 + ac];
                Al[ti][1] = alo[(r + 8) * ALD2 + ac];
                Al[ti][2] = alo[r * ALD2 + ac + 4];
                Al[ti][3] = alo[(r + 8) * ALD2 + ac + 4];
            }
#pragma unroll
            for (int ti = 0; ti < 4; ++ti)
#pragma unroll
                for (int tj = 0; tj < 4; ++tj)
                    mma16(c[ti][tj], Al[ti][0], Al[ti][1], Al[ti][2], Al[ti][3],
                          Bh[tj][0], Bh[tj][1]);
#pragma unroll
            for (int tj = 0; tj < 4; ++tj) {
                const int nn = wn0 + 8 * tj + g;
                Bl[tj][0] = wlo[wr * WLD2 + nn];
                Bl[tj][1] = wlo[(wr + 4) * WLD2 + nn];
            }
#pragma unroll
            for (int ti = 0; ti < 4; ++ti)
#pragma unroll
                for (int tj = 0; tj < 4; ++tj)
                    mma16(c[ti][tj], Ah[ti][0], Ah[ti][1], Ah[ti][2], Ah[ti][3],
                          Bl[tj][0], Bl[tj][1]);
        }
        __syncthreads();
    }

    const int bb = m0 >> 11;
    const int which = (MODE == 0) ? (n0 / DIM) : 0;

#pragma unroll
    for (int ti = 0; ti < 4; ++ti) {
        const int m = m0 + wm0 + 16 * ti + g;
        const int s = m & (SEQ - 1);
#pragma unroll
        for (int tj = 0; tj < 4; ++tj) {
            const int n = n0 + wn0 + 8 * tj + 2 * tig;
            const float b0 = __ldg(&bias[n]);
            const float b1 = __ldg(&bias[n + 1]);
            float2 v0, v1;
            v0.x = c[ti][tj][0] + b0; v0.y = c[ti][tj][1] + b1;
            v1.x = c[ti][tj][2] + b0; v1.y = c[ti][tj][3] + b1;
            if (MODE == 1) {
                *(float2*)&out[(size_t)m * DIM + n] = v0;
                *(float2*)&out[(size_t)(m + 8) * DIM + n] = v1;
            } else {
                const int rem = n - which * DIM;
                const int h = rem >> 6, d = rem & 63;
                float* dst = (which == 0) ? g_q : (which == 1) ? g_k : g_v;
                float* base = dst + ((size_t)(bb * NH + h) * SEQ) * HD + d;
                *(float2*)&base[(size_t)s * HD] = v0;
                *(float2*)&base[(size_t)(s + 8) * HD] = v1;
            }
        }
    }
}

// ---------------------------------------------------------------------------
// Flash attention v5: bf16x3 mma for S and PV, fp32 softmax, causal.
// Block = 128 queries x one (b,h). 8 warps, each owns 16 rows x full 128 keys.
// S fragments stay in registers; P = split2(S) feeds PV directly (no smem P).
// ---------------------------------------------------------------------------
#define QLD 36    // u32 per row of Q/K pair arrays ([token][d2])
#define VLD 68    // u32 per row of V pair array ([j2][d])
#define OFF_QHI 0
#define OFF_QLO (128 * QLD)
#define OFF_KHI (2 * 128 * QLD)
#define OFF_KLO (OFF_KHI + 128 * QLD)
#define OFF_VHI (OFF_KHI + 2 * 128 * QLD)
#define OFF_VLO (OFF_VHI + 64 * VLD)
#define ATTN_SMEM_BYTES ((OFF_VLO + 64 * VLD) * 4)   // 108544

__global__ void __launch_bounds__(256, 1) attn5_kernel()
{
    extern __shared__ uint32_t su[];
    uint32_t* Qhi = su + OFF_QHI;
    uint32_t* Qlo = su + OFF_QLO;
    uint32_t* Khi = su + OFF_KHI;
    uint32_t* Klo = su + OFF_KLO;
    uint32_t* Vhi = su + OFF_VHI;
    uint32_t* Vlo = su + OFF_VLO;

    const int bh = blockIdx.x;
    const int qi = (gridDim.y - 1) - blockIdx.y;   // heavy tiles first
    const int q0 = qi * 128;

    const float* Qg = g_q + (size_t)bh * SEQ * HD;
    const float* Kg = g_k + (size_t)bh * SEQ * HD;
    const float* Vg = g_v + (size_t)bh * SEQ * HD;

    const int tid = threadIdx.x;
    const int lane = tid & 31;
    const int warp = tid >> 5;
    const int g = lane >> 2;
    const int tig = lane & 3;
    const int r_lo = q0 + 16 * warp + g;      // this lane's row (and +8)

    // ---- convert Q tile -> hi/lo pairs in smem (0.125 folded in) ----
#pragma unroll
    for (int t = 0; t < 8; ++t) {
        const int f = tid + t * 256;
        const int j = f >> 4;
        const int d4 = f & 15;
        float4 q = *(const float4*)&Qg[((size_t)q0 + j) * HD + 4 * d4];
        uint32_t h0, l0, h1, l1;
        split2(q.x * 0.125f, q.y * 0.125f, h0, l0);
        split2(q.z * 0.125f, q.w * 0.125f, h1, l1);
        *(unsigned long long*)&Qhi[j * QLD + 2 * d4] =
            (unsigned long long)h0 | ((unsigned long long)h1 << 32);
        *(unsigned long long*)&Qlo[j * QLD + 2 * d4] =
            (unsigned long long)l0 | ((unsigned long long)l1 << 32);
    }

    float o[8][4];
#pragma unroll
    for (int dn = 0; dn < 8; ++dn)
#pragma unroll
        for (int e = 0; e < 4; ++e) o[dn][e] = 0.f;
    float mrow[2] = {neg_inf(), neg_inf()};
    float lrow[2] = {0.f, 0.f};

    for (int kt = 0; kt <= qi; ++kt) {
        __syncthreads();    // previous-iter reads of K/V done (also covers Q write, iter 0)

        // ---- K tile -> pair-packed hi/lo [token][d2] ----
#pragma unroll
        for (int t = 0; t < 8; ++t) {
            const int f = tid + t * 256;
            const int j = f >> 4;
            const int d4 = f & 15;
            float4 kv = *(const float4*)&Kg[((size_t)kt * 128 + j) * HD + 4 * d4];
            uint32_t h0, l0, h1, l1;
            split2(kv.x, kv.y, h0, l0);
            split2(kv.z, kv.w, h1, l1);
            *(unsigned long long*)&Khi[j * QLD + 2 * d4] =
                (unsigned long long)h0 | ((unsigned long long)h1 << 32);
            *(unsigned long long*)&Klo[j * QLD + 2 * d4] =
                (unsigned long long)l0 | ((unsigned long long)l1 << 32);
        }
        // ---- V tile -> pair-packed over j: [j2][d] ----
#pragma unroll
        for (int t = 0; t < 4; ++t) {
            const int f = tid + t * 256;
            const int j2 = f >> 4;
            const int d4 = f & 15;
            const float4 va = *(const float4*)&Vg[((size_t)kt * 128 + 2 * j2) * HD + 4 * d4];
            const float4 vb = *(const float4*)&Vg[((size_t)kt * 128 + 2 * j2 + 1) * HD + 4 * d4];
            uint4 hv, lv;
            split2(va.x, vb.x, hv.x, lv.x);
            split2(va.y, vb.y, hv.y, lv.y);
            split2(va.z, vb.z, hv.z, lv.z);
            split2(va.w, vb.w, hv.w, lv.w);
            *(uint4*)&Vhi[j2 * VLD + 4 * d4] = hv;
            *(uint4*)&Vlo[j2 * VLD + 4 * d4] = lv;
        }
        __syncthreads();

        // ---- S = Q K^T (scaled): 16 n-tiles x 4 k16 x 3 passes ----
        float c[16][4];
#pragma unroll
        for (int t = 0; t < 16; ++t)
#pragma unroll
            for (int e = 0; e < 4; ++e) c[t][e] = 0.f;

#pragma unroll
        for (int k16 = 0; k16 < 4; ++k16) {
            const int ab = (16 * warp + g) * QLD + 8 * k16 + tig;
            uint32_t Ah[4], Al[4];
            Ah[0] = Qhi[ab];            Ah[1] = Qhi[ab + 8 * QLD];
            Ah[2] = Qhi[ab + 4];        Ah[3] = Qhi[ab + 8 * QLD + 4];
            Al[0] = Qlo[ab];            Al[1] = Qlo[ab + 8 * QLD];
            Al[2] = Qlo[ab + 4];        Al[3] = Qlo[ab + 8 * QLD + 4];
#pragma unroll
            for (int t = 0; t < 16; ++t) {
                const int kb = (8 * t + g) * QLD + 8 * k16 + tig;
                const uint32_t Bh0 = Khi[kb], Bh1 = Khi[kb + 4];
                mma16(c[t], Ah[0], Ah[1], Ah[2], Ah[3], Bh0, Bh1);
                mma16(c[t], Al[0], Al[1], Al[2], Al[3], Bh0, Bh1);
                const uint32_t Bl0 = Klo[kb], Bl1 = Klo[kb + 4];
                mma16(c[t], Ah[0], Ah[1], Ah[2], Ah[3], Bl0, Bl1);
            }
        }

        // ---- online softmax (rows g and g+8 of this warp's 16) ----
        const bool diag = (kt == qi);
#pragma unroll
        for (int row = 0; row < 2; ++row) {
            const int rg = r_lo + 8 * row;
            if (diag) {
#pragma unroll
                for (int t = 0; t < 16; ++t) {
                    const int j = kt * 128 + 8 * t + 2 * tig;
                    if (j > rg)     c[t][2 * row]     = neg_inf();
                    if (j + 1 > rg) c[t][2 * row + 1] = neg_inf();
                }
            }
            float mx = neg_inf();
#pragma unroll
            for (int t = 0; t < 16; ++t)
                mx = fmaxf(mx, fmaxf(c[t][2 * row], c[t][2 * row + 1]));
            mx = fmaxf(mx, __shfl_xor_sync(0xffffffffu, mx, 1));
            mx = fmaxf(mx, __shfl_xor_sync(0xffffffffu, mx, 2));
            const float mn = fmaxf(mrow[row], mx);
            const float corr = __expf(mrow[row] - mn);
            float rs = 0.f;
#pragma unroll
            for (int t = 0; t < 16; ++t) {
                const float p0 = __expf(c[t][2 * row] - mn);
                const float p1 = __expf(c[t][2 * row + 1] - mn);
                c[t][2 * row] = p0;
                c[t][2 * row + 1] = p1;
                rs += p0 + p1;
            }
            rs += __shfl_xor_sync(0xffffffffu, rs, 1);
            rs += __shfl_xor_sync(0xffffffffu, rs, 2);
            lrow[row] = lrow[row] * corr + rs;
            mrow[row] = mn;
#pragma unroll
            for (int dn = 0; dn < 8; ++dn) {
                o[dn][2 * row] *= corr;
                o[dn][2 * row + 1] *= corr;
            }
        }

        // ---- O += P V : P fragments direct from S registers ----
#pragma unroll
        for (int kk = 0; kk < 8; ++kk) {
            uint32_t Ph[4], Pl[4];
            split2(c[2 * kk][0],     c[2 * kk][1],     Ph[0], Pl[0]);
            split2(c[2 * kk][2],     c[2 * kk][3],     Ph[1], Pl[1]);
            split2(c[2 * kk + 1][0], c[2 * kk + 1][1], Ph[2], Pl[2]);
            split2(c[2 * kk + 1][2], c[2 * kk + 1][3], Ph[3], Pl[3]);
#pragma unroll
            for (int dn = 0; dn < 8; ++dn) {
                const int vb = (8 * kk + tig) * VLD + 8 * dn + g;
                const uint32_t Vh0 = Vhi[vb], Vh1 = Vhi[vb + 4 * VLD];
                mma16(o[dn], Ph[0], Ph[1], Ph[2], Ph[3], Vh0, Vh1);
                mma16(o[dn], Pl[0], Pl[1], Pl[2], Pl[3], Vh0, Vh1);
                const uint32_t Vl0 = Vlo[vb], Vl1 = Vlo[vb + 4 * VLD];
                mma16(o[dn], Ph[0], Ph[1], Ph[2], Ph[3], Vl0, Vl1);
            }
        }
    }

    // ---- write normalized output ----
    const int bb = bh / NH;
    const int h = bh - bb * NH;
#pragma unroll
    for (int row = 0; row < 2; ++row) {
        const int r = r_lo + 8 * row;
        const float inv = 1.f / lrow[row];
        float* dst = &g_attn[((size_t)(bb * SEQ) + r) * DIM + h * HD + 2 * tig];
#pragma unroll
        for (int dn = 0; dn < 8; ++dn) {
            float2 w;
            w.x = o[dn][2 * row] * inv;
            w.y = o[dn][2 * row + 1] * inv;
            *(float2*)&dst[8 * dn] = w;
        }
    }
}

// ---------------------------------------------------------------------------
extern "C" void kernel_launch(void* const* d_in, const int* in_sizes, int n_in,
                              void* d_out, int out_size)
{
    const float* x     = (const float*)d_in[0];
    const float* Wqkv  = (const float*)d_in[1];
    const float* bqkv  = (const float*)d_in[2];
    const float* Wproj = (const float*)d_in[3];
    const float* bproj = (const float*)d_in[4];
    float* out = (float*)d_out;

    cudaFuncSetAttribute(attn5_kernel,
                         cudaFuncAttributeMaxDynamicSharedMemorySize, ATTN_SMEM_BYTES);

    gemm_bf3_kernel<NQKV, 0><<<dim3(NQKV / 128, M_TOT / 128), 256, GEMM_SMEM_BYTES>>>(
        x, Wqkv, bqkv, nullptr);
    attn5_kernel<<<dim3(BSZ * NH, SEQ / 128), 256, ATTN_SMEM_BYTES>>>();
    gemm_bf3_kernel<DIM, 1><<<dim3(DIM / 128, M_TOT / 128), 256, GEMM_SMEM_BYTES>>>(
        nullptr, Wproj, bproj, out);
}